// round 9
// baseline (speedup 1.0000x reference)
#include <cuda_runtime.h>
#include <cuda_bf16.h>
#include <math.h>

#define NROWS 384
#define SLEN  1024
#define CIN   256
#define CH    32
#define NH    8
#define HC    256   // NH*CH

// Scratch (no cudaMalloc allowed).
__device__ float g_q_buf[NROWS * HC];
__device__ float g_o_buf[NROWS * HC];
__device__ float g_k_buf[(size_t)NROWS * SLEN * CH];
__device__ float g_v_buf[(size_t)NROWS * SLEN * CH];
// Pre-split weights (bf16 hi/lo) for tensor-core paths.
__device__ __nv_bfloat16 g_WgHi[CIN * HC], g_WgLo[CIN * HC];
__device__ __nv_bfloat16 g_WoHi[HC * CIN], g_WoLo[HC * CIN];
__device__ __nv_bfloat16 g_WkvHi[CIN * 64], g_WkvLo[CIN * 64];  // Wk|Wv combined
// Masked-mean partials: [tile 0..7][n][c] and [tile][n]
__device__ float g_qpart[8 * NROWS * CIN];
__device__ float g_mpart[8 * NROWS];

// ---------------------------------------------------------------------------
// cp.async helpers
// ---------------------------------------------------------------------------
__device__ __forceinline__ void cp16(unsigned saddr, const void* g) {
    asm volatile("cp.async.cg.shared.global [%0], [%1], 16;" :: "r"(saddr), "l"(g));
}
#define CP_COMMIT() asm volatile("cp.async.commit_group;" ::: "memory")
#define CP_WAIT1()  asm volatile("cp.async.wait_group 1;" ::: "memory")
#define CP_WAIT0()  asm volatile("cp.async.wait_group 0;" ::: "memory")

// ---------------------------------------------------------------------------
// Kernel 0: split Wg, Wo, Wk|Wv into bf16 hi/lo
// ---------------------------------------------------------------------------
__global__ void wconv_kernel(const float* __restrict__ Wg,
                             const float* __restrict__ Wo,
                             const float* __restrict__ Wk,
                             const float* __restrict__ Wv) {
    int i = (blockIdx.x * 256 + threadIdx.x) * 4;  // 65536 elems per big matrix
    {
        float4 v = *reinterpret_cast<const float4*>(Wg + i);
        __nv_bfloat162 h01 = __floats2bfloat162_rn(v.x, v.y);
        __nv_bfloat162 h23 = __floats2bfloat162_rn(v.z, v.w);
        __nv_bfloat162 l01 = __floats2bfloat162_rn(v.x - __low2float(h01),
                                                   v.y - __high2float(h01));
        __nv_bfloat162 l23 = __floats2bfloat162_rn(v.z - __low2float(h23),
                                                   v.w - __high2float(h23));
        *reinterpret_cast<__nv_bfloat162*>(g_WgHi + i)     = h01;
        *reinterpret_cast<__nv_bfloat162*>(g_WgHi + i + 2) = h23;
        *reinterpret_cast<__nv_bfloat162*>(g_WgLo + i)     = l01;
        *reinterpret_cast<__nv_bfloat162*>(g_WgLo + i + 2) = l23;
    }
    {
        float4 v = *reinterpret_cast<const float4*>(Wo + i);
        __nv_bfloat162 h01 = __floats2bfloat162_rn(v.x, v.y);
        __nv_bfloat162 h23 = __floats2bfloat162_rn(v.z, v.w);
        __nv_bfloat162 l01 = __floats2bfloat162_rn(v.x - __low2float(h01),
                                                   v.y - __high2float(h01));
        __nv_bfloat162 l23 = __floats2bfloat162_rn(v.z - __low2float(h23),
                                                   v.w - __high2float(h23));
        *reinterpret_cast<__nv_bfloat162*>(g_WoHi + i)     = h01;
        *reinterpret_cast<__nv_bfloat162*>(g_WoHi + i + 2) = h23;
        *reinterpret_cast<__nv_bfloat162*>(g_WoLo + i)     = l01;
        *reinterpret_cast<__nv_bfloat162*>(g_WoLo + i + 2) = l23;
    }
    if (i < CIN * 64) {  // combined Wk|Wv: row k, col j (j<32 => Wk, else Wv)
        int k = i >> 6, j = i & 63;
        float4 v = (j < 32)
            ? *reinterpret_cast<const float4*>(Wk + k * CH + j)
            : *reinterpret_cast<const float4*>(Wv + k * CH + (j - 32));
        __nv_bfloat162 h01 = __floats2bfloat162_rn(v.x, v.y);
        __nv_bfloat162 h23 = __floats2bfloat162_rn(v.z, v.w);
        __nv_bfloat162 l01 = __floats2bfloat162_rn(v.x - __low2float(h01),
                                                   v.y - __high2float(h01));
        __nv_bfloat162 l23 = __floats2bfloat162_rn(v.z - __low2float(h23),
                                                   v.w - __high2float(h23));
        *reinterpret_cast<__nv_bfloat162*>(g_WkvHi + i)     = h01;
        *reinterpret_cast<__nv_bfloat162*>(g_WkvHi + i + 2) = h23;
        *reinterpret_cast<__nv_bfloat162*>(g_WkvLo + i)     = l01;
        *reinterpret_cast<__nv_bfloat162*>(g_WkvLo + i + 2) = l23;
    }
}

// ---------------------------------------------------------------------------
// MMA helpers (bf16x3 split)
// ---------------------------------------------------------------------------
__device__ __forceinline__ void ldsm4(unsigned r[4], unsigned addr) {
    asm volatile("ldmatrix.sync.aligned.m8n8.x4.shared.b16 {%0,%1,%2,%3}, [%4];"
        : "=r"(r[0]), "=r"(r[1]), "=r"(r[2]), "=r"(r[3]) : "r"(addr));
}
__device__ __forceinline__ void ldsm4t(unsigned r[4], unsigned addr) {
    asm volatile("ldmatrix.sync.aligned.m8n8.x4.trans.shared.b16 {%0,%1,%2,%3}, [%4];"
        : "=r"(r[0]), "=r"(r[1]), "=r"(r[2]), "=r"(r[3]) : "r"(addr));
}
__device__ __forceinline__ void mma_bf16(float c[4], const unsigned a[4],
                                         unsigned b0, unsigned b1) {
    asm volatile("mma.sync.aligned.m16n8k16.row.col.f32.bf16.bf16.f32 "
        "{%0,%1,%2,%3}, {%4,%5,%6,%7}, {%8,%9}, {%0,%1,%2,%3};"
        : "+f"(c[0]), "+f"(c[1]), "+f"(c[2]), "+f"(c[3])
        : "r"(a[0]), "r"(a[1]), "r"(a[2]), "r"(a[3]), "r"(b0), "r"(b1));
}

__device__ __forceinline__ void split_store(char* ph, char* pl, float4 v) {
    __nv_bfloat162 h01 = __floats2bfloat162_rn(v.x, v.y);
    __nv_bfloat162 h23 = __floats2bfloat162_rn(v.z, v.w);
    __nv_bfloat162 l01 = __floats2bfloat162_rn(v.x - __low2float(h01),
                                               v.y - __high2float(h01));
    __nv_bfloat162 l23 = __floats2bfloat162_rn(v.z - __low2float(h23),
                                               v.w - __high2float(h23));
    reinterpret_cast<__nv_bfloat162*>(ph)[0] = h01;
    reinterpret_cast<__nv_bfloat162*>(ph)[1] = h23;
    reinterpret_cast<__nv_bfloat162*>(pl)[0] = l01;
    reinterpret_cast<__nv_bfloat162*>(pl)[1] = l23;
}

// ---------------------------------------------------------------------------
// Kernel 2: k|v = m @ (Wk|Wv), bf16x3 tensor path + fused masked-mean partials.
// CTA = 128 tokens (row n = blockIdx>>3, tile = blockIdx&7), 256 threads.
// cp.async double-buffered weight chunks.
// ---------------------------------------------------------------------------
#define KA_STR  264
#define KAH_OFF 0                 // 128 x 264 bf16 = 67584 B
#define KAL_OFF 67584
#define KB_STR  72
#define KB0_OFF 135168            // stage s at KB0 + s*4608; hi then lo (+2304)
#define KV_SMEM 144384

__device__ __forceinline__ void kv_prefetch(unsigned sbase, int stage, int kk, int t) {
    int f = t & 127;
    int row = f >> 3, c8 = (f & 7) << 3;
    unsigned dst = sbase + KB0_OFF + stage * 4608 + ((t < 128) ? 0 : 2304)
                 + (row * KB_STR + c8) * 2;
    const __nv_bfloat16* src = ((t < 128) ? g_WkvHi : g_WkvLo) + (kk + row) * 64 + c8;
    cp16(dst, src);
}

__global__ void __launch_bounds__(256)
kv_kernel(const float* __restrict__ m, const float* __restrict__ mask) {
    extern __shared__ char smc[];
    __shared__ float mask_sm[128];
    unsigned sbase = (unsigned)__cvta_generic_to_shared(smc);
    int t = threadIdx.x;
    int lane = t & 31, wm = t >> 5;
    int n    = blockIdx.x >> 3;
    int tile = blockIdx.x & 7;
    long r0g = (long)blockIdx.x * 128;

    if (t < 128) mask_sm[t] = mask[(size_t)n * SLEN + tile * 128 + t];

    // load m tile [128][256] fp32, split into hi/lo smem
    #pragma unroll
    for (int i = 0; i < 32; i++) {
        int idx = t + i * 256;
        int row = idx >> 6;
        int c4  = (idx & 63) << 2;
        float4 v = *reinterpret_cast<const float4*>(m + (r0g + row) * CIN + c4);
        split_store(smc + KAH_OFF + (row * KA_STR + c4) * 2,
                    smc + KAL_OFF + (row * KA_STR + c4) * 2, v);
    }
    __syncthreads();

    // prefetch weight chunk 0 while computing mean partials
    kv_prefetch(sbase, 0, 0, t);
    CP_COMMIT();

    // masked-mean partial for channel t over this CTA's 128 tokens
    {
        float qs = 0.f;
        #pragma unroll 8
        for (int r = 0; r < 128; r++) {
            float hi = __bfloat162float(*reinterpret_cast<__nv_bfloat16*>(
                smc + KAH_OFF + (r * KA_STR + t) * 2));
            float lo = __bfloat162float(*reinterpret_cast<__nv_bfloat16*>(
                smc + KAL_OFF + (r * KA_STR + t) * 2));
            qs = fmaf(hi + lo, mask_sm[r], qs);
        }
        g_qpart[(tile * NROWS + n) * CIN + t] = qs;
        if (t == 0) {
            float ms = 0.f;
            for (int r = 0; r < 128; r++) ms += mask_sm[r];
            g_mpart[tile * NROWS + n] = ms;
        }
    }

    float acc[8][4];
    #pragma unroll
    for (int i = 0; i < 8; i++)
        #pragma unroll
        for (int j = 0; j < 4; j++) acc[i][j] = 0.f;

    for (int c = 0; c < 16; c++) {
        if (c < 15) { kv_prefetch(sbase, (c + 1) & 1, (c + 1) * 16, t); CP_COMMIT(); CP_WAIT1(); }
        else        { CP_WAIT0(); }
        __syncthreads();
        int kk = c * 16, s = c & 1;
        unsigned kbh = sbase + KB0_OFF + s * 4608;

        unsigned ah[4], al[4];
        unsigned aaddr = sbase + KAH_OFF +
            ((wm * 16 + (lane & 15)) * KA_STR + kk + ((lane >> 4) << 3)) * 2;
        ldsm4(ah, aaddr);
        ldsm4(al, aaddr + KAL_OFF);

        #pragma unroll
        for (int nb = 0; nb < 4; nb++) {
            unsigned baddr = kbh +
                ((lane & 15) * KB_STR + nb * 16 + ((lane >> 4) << 3)) * 2;
            unsigned bh[4], bl[4];
            ldsm4t(bh, baddr);
            ldsm4t(bl, baddr + 2304);
            mma_bf16(acc[nb * 2],     ah, bh[0], bh[1]);
            mma_bf16(acc[nb * 2],     ah, bl[0], bl[1]);
            mma_bf16(acc[nb * 2],     al, bh[0], bh[1]);
            mma_bf16(acc[nb * 2 + 1], ah, bh[2], bh[3]);
            mma_bf16(acc[nb * 2 + 1], ah, bl[2], bl[3]);
            mma_bf16(acc[nb * 2 + 1], al, bh[2], bh[3]);
        }
        __syncthreads();
    }

    // write k (cols 0..31) and v (cols 32..63)
    #pragma unroll
    for (int nb = 0; nb < 4; nb++) {
        #pragma unroll
        for (int half = 0; half < 2; half++) {
            int col = nb * 16 + half * 8 + (lane & 3) * 2;
            int r0  = wm * 16 + (lane >> 2);
            float* f = acc[nb * 2 + half];
            float* dst = (col < CH) ? (g_k_buf + ((r0g + r0) * CH + col))
                                    : (g_v_buf + ((r0g + r0) * CH + col - CH));
            *reinterpret_cast<float2*>(dst) = make_float2(f[0], f[1]);
            dst += 8 * CH;
            *reinterpret_cast<float2*>(dst) = make_float2(f[2], f[3]);
        }
    }
}

// ---------------------------------------------------------------------------
// Kernel 2b: finish mean + q = (mean @ Wq) * C^-0.5   (tiny)
// ---------------------------------------------------------------------------
__global__ void q2_kernel(const float* __restrict__ Wq) {
    int n = blockIdx.x, t = threadIdx.x;
    __shared__ float qm[CIN];
    float s = 0.f;
    #pragma unroll
    for (int p = 0; p < 8; p++) s += g_qpart[(p * NROWS + n) * CIN + t];
    float mk = 0.f;
    #pragma unroll
    for (int p = 0; p < 8; p++) mk += g_mpart[p * NROWS + n];
    qm[t] = s / (mk + 1e-10f);
    __syncthreads();
    float acc = 0.f;
    #pragma unroll 8
    for (int c = 0; c < CIN; c++) acc = fmaf(qm[c], Wq[c * HC + t], acc);
    g_q_buf[n * HC + t] = acc * 0.17677669529663687f;
}

// ---------------------------------------------------------------------------
// Kernel 3: attention (logits + softmax + p@v), fp32
// ---------------------------------------------------------------------------
__global__ void __launch_bounds__(256, 2)
attn_kernel(const float* __restrict__ mask) {
    int n = blockIdx.x, t = threadIdx.x;
    __shared__ float q_sm[HC];
    __shared__ float p_sm[NH * SLEN];

    q_sm[t] = g_q_buf[n * HC + t];
    __syncthreads();

    const float* krow = g_k_buf + (size_t)n * SLEN * CH;
    const float* vrow = g_v_buf + (size_t)n * SLEN * CH;
    const float* mk   = mask + (size_t)n * SLEN;

    for (int s = t; s < SLEN; s += 256) {
        float kreg[32];
        #pragma unroll
        for (int q = 0; q < 8; q++)
            *reinterpret_cast<float4*>(kreg + q * 4) =
                *reinterpret_cast<const float4*>(krow + (size_t)s * CH + q * 4);
        float bias = 1e9f * (mk[s] - 1.0f);
        #pragma unroll
        for (int h = 0; h < NH; h++) {
            float d = 0.f;
            #pragma unroll
            for (int j = 0; j < 32; j++) d = fmaf(q_sm[h * 32 + j], kreg[j], d);
            p_sm[h * SLEN + s] = d + bias;
        }
    }
    __syncthreads();

    int h = t >> 5, lane = t & 31;
    float mx = -3.0e38f;
    for (int s = lane; s < SLEN; s += 32) mx = fmaxf(mx, p_sm[h * SLEN + s]);
    #pragma unroll
    for (int off = 16; off > 0; off >>= 1)
        mx = fmaxf(mx, __shfl_xor_sync(0xffffffffu, mx, off));

    float sum = 0.f;
    for (int s = lane; s < SLEN; s += 32) {
        float e = __expf(p_sm[h * SLEN + s] - mx);
        p_sm[h * SLEN + s] = e;
        sum += e;
    }
    #pragma unroll
    for (int off = 16; off > 0; off >>= 1)
        sum += __shfl_xor_sync(0xffffffffu, sum, off);
    float inv = 1.f / sum;
    for (int s = lane; s < SLEN; s += 32) p_sm[h * SLEN + s] *= inv;
    __syncthreads();

    {
        int sg  = lane >> 3;
        int c4  = (lane & 7) << 2;
        float4 acc4 = make_float4(0.f, 0.f, 0.f, 0.f);
        const float* ph = p_sm + h * SLEN;
        #pragma unroll 4
        for (int s = sg; s < SLEN; s += 4) {
            float p = ph[s];
            float4 v4 = *reinterpret_cast<const float4*>(vrow + (size_t)s * CH + c4);
            acc4.x = fmaf(p, v4.x, acc4.x);
            acc4.y = fmaf(p, v4.y, acc4.y);
            acc4.z = fmaf(p, v4.z, acc4.z);
            acc4.w = fmaf(p, v4.w, acc4.w);
        }
        #pragma unroll
        for (int off = 8; off <= 16; off <<= 1) {
            acc4.x += __shfl_xor_sync(0xffffffffu, acc4.x, off);
            acc4.y += __shfl_xor_sync(0xffffffffu, acc4.y, off);
            acc4.z += __shfl_xor_sync(0xffffffffu, acc4.z, off);
            acc4.w += __shfl_xor_sync(0xffffffffu, acc4.w, off);
        }
        if (sg == 0)
            *reinterpret_cast<float4*>(g_o_buf + n * HC + h * CH + c4) = acc4;
    }
}

// ---------------------------------------------------------------------------
// Kernel 4: tensor-core out_kernel (bf16x3), BM=64, 256 threads, 2 CTAs/SM,
// cp.async double-buffered weight chunks.
// ---------------------------------------------------------------------------
#define A_STR   264
#define AH_OFF  0                 // 64 x 264 bf16 = 33792 B
#define AL_OFF  33792
#define B0_OFF  67584             // stage s at B0 + s*16896; hi then lo (+8448)
#define BG_OFF  101376
#define OV_OFF  102400
#define BO_OFF  103424
#define SMEM_BYTES 104448

__device__ __forceinline__ void out_prefetch(unsigned sbase, int stage,
        const __nv_bfloat16* __restrict__ WHi,
        const __nv_bfloat16* __restrict__ WLo, int kk, int t) {
    unsigned bh = sbase + B0_OFF + stage * 16896;
    #pragma unroll
    for (int i = 0; i < 2; i++) {
        int f = t + i * 256;
        int row = f >> 5, c8 = (f & 31) << 3;
        unsigned off = (row * A_STR + c8) * 2;
        cp16(bh + off,        WHi + (kk + row) * 256 + c8);
        cp16(bh + 8448 + off, WLo + (kk + row) * 256 + c8);
    }
}

__device__ __forceinline__ void gemm_bf16x3(
    unsigned sbase,
    const __nv_bfloat16* __restrict__ WHi,
    const __nv_bfloat16* __restrict__ WLo,
    float acc[16][4], int t, int lane, int wm, int wn)
{
    out_prefetch(sbase, 0, WHi, WLo, 0, t);
    CP_COMMIT();
    for (int c = 0; c < 16; c++) {
        if (c < 15) { out_prefetch(sbase, (c + 1) & 1, WHi, WLo, (c + 1) * 16, t);
                      CP_COMMIT(); CP_WAIT1(); }
        else        { CP_WAIT0(); }
        __syncthreads();
        int kk = c * 16, s = c & 1;
        unsigned bhb = sbase + B0_OFF + s * 16896;

        unsigned ah[4], al[4];
        unsigned aaddr = sbase + AH_OFF +
            ((wm * 16 + (lane & 15)) * A_STR + kk + ((lane >> 4) << 3)) * 2;
        ldsm4(ah, aaddr);
        ldsm4(al, aaddr + AL_OFF);

        #pragma unroll
        for (int nb = 0; nb < 8; nb++) {
            int n0 = wn * 128 + nb * 16;
            unsigned baddr = bhb +
                ((lane & 15) * A_STR + n0 + ((lane >> 4) << 3)) * 2;
            unsigned bh4[4], bl4[4];
            ldsm4t(bh4, baddr);
            ldsm4t(bl4, baddr + 8448);
            mma_bf16(acc[nb * 2],     ah, bh4[0], bh4[1]);
            mma_bf16(acc[nb * 2],     ah, bl4[0], bl4[1]);
            mma_bf16(acc[nb * 2],     al, bh4[0], bh4[1]);
            mma_bf16(acc[nb * 2 + 1], ah, bh4[2], bh4[3]);
            mma_bf16(acc[nb * 2 + 1], ah, bl4[2], bl4[3]);
            mma_bf16(acc[nb * 2 + 1], al, bh4[2], bh4[3]);
        }
        __syncthreads();
    }
}

__global__ void __launch_bounds__(256, 2)
out_kernel(const float* __restrict__ m,
           const float* __restrict__ bg,
           const float* __restrict__ bo,
           float* __restrict__ out) {
    extern __shared__ char smc[];
    unsigned sbase = (unsigned)__cvta_generic_to_shared(smc);
    float* sBG = reinterpret_cast<float*>(smc + BG_OFF);
    float* sOV = reinterpret_cast<float*>(smc + OV_OFF);
    float* sBO = reinterpret_cast<float*>(smc + BO_OFF);

    int t = threadIdx.x;
    int lane = t & 31, wid = t >> 5;
    int wm = wid >> 1, wn = wid & 1;
    int n = blockIdx.y;
    long tok0 = (long)n * SLEN + (long)blockIdx.x * 64;

    sBG[t] = bg[t];
    sOV[t] = g_o_buf[n * HC + t];
    sBO[t] = bo[t];

    // load m tile [64][256] fp32 once, split into bf16 hi/lo smem
    #pragma unroll
    for (int i = 0; i < 16; i++) {
        int idx = t + i * 256;
        int row = idx >> 6;
        int c4  = (idx & 63) << 2;
        float4 v = *reinterpret_cast<const float4*>(m + (tok0 + row) * CIN + c4);
        split_store(smc + AH_OFF + (row * A_STR + c4) * 2,
                    smc + AL_OFF + (row * A_STR + c4) * 2, v);
    }
    __syncthreads();

    float acc[16][4];
    #pragma unroll
    for (int i = 0; i < 16; i++)
        #pragma unroll
        for (int j = 0; j < 4; j++) acc[i][j] = 0.f;

    // ---- GEMM1: M @ Wg ----
    gemm_bf16x3(sbase, g_WgHi, g_WgLo, acc, t, lane, wm, wn);

    // ---- epilogue 1: G = ov * sigmoid(acc + bg), split back into Ah/Al ----
    #pragma unroll
    for (int nt = 0; nt < 16; nt++) {
        int col0 = wn * 128 + nt * 8 + (lane & 3) * 2;
        int r0   = wm * 16 + (lane >> 2);
        float bg0 = sBG[col0], bg1 = sBG[col0 + 1];
        float ov0 = sOV[col0], ov1 = sOV[col0 + 1];
        float g0 = ov0 / (1.f + __expf(-(acc[nt][0] + bg0)));
        float g1 = ov1 / (1.f + __expf(-(acc[nt][1] + bg1)));
        float g2 = ov0 / (1.f + __expf(-(acc[nt][2] + bg0)));
        float g3 = ov1 / (1.f + __expf(-(acc[nt][3] + bg1)));
        __nv_bfloat162 h01 = __floats2bfloat162_rn(g0, g1);
        __nv_bfloat162 l01 = __floats2bfloat162_rn(g0 - __low2float(h01),
                                                   g1 - __high2float(h01));
        __nv_bfloat162 h23 = __floats2bfloat162_rn(g2, g3);
        __nv_bfloat162 l23 = __floats2bfloat162_rn(g2 - __low2float(h23),
                                                   g3 - __high2float(h23));
        *reinterpret_cast<__nv_bfloat162*>(smc + AH_OFF + (r0 * A_STR + col0) * 2)       = h01;
        *reinterpret_cast<__nv_bfloat162*>(smc + AL_OFF + (r0 * A_STR + col0) * 2)       = l01;
        *reinterpret_cast<__nv_bfloat162*>(smc + AH_OFF + ((r0 + 8) * A_STR + col0) * 2) = h23;
        *reinterpret_cast<__nv_bfloat162*>(smc + AL_OFF + ((r0 + 8) * A_STR + col0) * 2) = l23;
        acc[nt][0] = acc[nt][1] = acc[nt][2] = acc[nt][3] = 0.f;
    }
    __syncthreads();

    // ---- GEMM2: G @ Wo ----
    gemm_bf16x3(sbase, g_WoHi, g_WoLo, acc, t, lane, wm, wn);

    // ---- epilogue 2: + bo, write out ----
    #pragma unroll
    for (int nt = 0; nt < 16; nt++) {
        int col0 = wn * 128 + nt * 8 + (lane & 3) * 2;
        int r0   = wm * 16 + (lane >> 2);
        float2 o0 = make_float2(acc[nt][0] + sBO[col0], acc[nt][1] + sBO[col0 + 1]);
        float2 o1 = make_float2(acc[nt][2] + sBO[col0], acc[nt][3] + sBO[col0 + 1]);
        *reinterpret_cast<float2*>(out + (tok0 + r0) * CIN + col0)     = o0;
        *reinterpret_cast<float2*>(out + (tok0 + r0 + 8) * CIN + col0) = o1;
    }
}

// ---------------------------------------------------------------------------
extern "C" void kernel_launch(void* const* d_in, const int* in_sizes, int n_in,
                              void* d_out, int out_size) {
    const float* m    = (const float*)d_in[0];
    const float* mask = (const float*)d_in[1];
    const float* Wq   = (const float*)d_in[2];
    const float* Wk   = (const float*)d_in[3];
    const float* Wv   = (const float*)d_in[4];
    const float* Wg   = (const float*)d_in[5];
    const float* bg   = (const float*)d_in[6];
    const float* Wo   = (const float*)d_in[7];
    const float* bo   = (const float*)d_in[8];
    float* out = (float*)d_out;

    wconv_kernel<<<64, 256>>>(Wg, Wo, Wk, Wv);

    cudaFuncSetAttribute(kv_kernel,
                         cudaFuncAttributeMaxDynamicSharedMemorySize, KV_SMEM);
    kv_kernel<<<(NROWS * SLEN) / 128, 256, KV_SMEM>>>(m, mask);

    q2_kernel<<<NROWS, 256>>>(Wq);

    attn_kernel<<<NROWS, 256>>>(mask);

    cudaFuncSetAttribute(out_kernel,
                         cudaFuncAttributeMaxDynamicSharedMemorySize, SMEM_BYTES);
    out_kernel<<<dim3(SLEN / 64, NROWS), 256, SMEM_BYTES>>>(m, bg, bo, out);
}

// round 11
// speedup vs baseline: 1.1025x; 1.1025x over previous
#include <cuda_runtime.h>
#include <cuda_bf16.h>
#include <math.h>

#define NROWS 384
#define SLEN  1024
#define CIN   256
#define CH    32
#define NH    8
#define HC    256   // NH*CH

// Scratch (no cudaMalloc allowed).
__device__ float g_q_buf[NROWS * HC];
__device__ float g_o_buf[NROWS * HC];
__device__ float g_k_buf[(size_t)NROWS * SLEN * CH];
__device__ float g_v_buf[(size_t)NROWS * SLEN * CH];
// Pre-split weights (bf16 hi/lo), K-major for mma.sync streaming.
__device__ __nv_bfloat16 g_WgHi[CIN * HC], g_WgLo[CIN * HC];
__device__ __nv_bfloat16 g_WoHi[HC * CIN], g_WoLo[HC * CIN];
__device__ __nv_bfloat16 g_WkvHi[CIN * 64], g_WkvLo[CIN * 64];  // Wk|Wv combined
// Masked-mean partials: [tile 0..15][n][c] and [tile][n]
__device__ float g_qpart[16 * NROWS * CIN];
__device__ float g_mpart[16 * NROWS];
// Split-S attention partials: [half][n][hc] and stats [half][n][h][2]
__device__ float g_opart[2 * NROWS * HC];
__device__ float g_stat[2 * NROWS * NH * 2];

// ---------------------------------------------------------------------------
// cp.async helpers
// ---------------------------------------------------------------------------
__device__ __forceinline__ void cp16(unsigned saddr, const void* g) {
    asm volatile("cp.async.cg.shared.global [%0], [%1], 16;" :: "r"(saddr), "l"(g));
}
#define CP_COMMIT() asm volatile("cp.async.commit_group;" ::: "memory")
#define CP_WAIT0()  asm volatile("cp.async.wait_group 0;" ::: "memory")

// ---------------------------------------------------------------------------
// Kernel 0: split Wg, Wo, Wk|Wv into bf16 hi/lo
// ---------------------------------------------------------------------------
__global__ void wconv_kernel(const float* __restrict__ Wg,
                             const float* __restrict__ Wo,
                             const float* __restrict__ Wk,
                             const float* __restrict__ Wv) {
    int i = (blockIdx.x * 256 + threadIdx.x) * 4;  // 65536 elems per big matrix
    {
        float4 v = *reinterpret_cast<const float4*>(Wg + i);
        __nv_bfloat162 h01 = __floats2bfloat162_rn(v.x, v.y);
        __nv_bfloat162 h23 = __floats2bfloat162_rn(v.z, v.w);
        __nv_bfloat162 l01 = __floats2bfloat162_rn(v.x - __low2float(h01),
                                                   v.y - __high2float(h01));
        __nv_bfloat162 l23 = __floats2bfloat162_rn(v.z - __low2float(h23),
                                                   v.w - __high2float(h23));
        *reinterpret_cast<__nv_bfloat162*>(g_WgHi + i)     = h01;
        *reinterpret_cast<__nv_bfloat162*>(g_WgHi + i + 2) = h23;
        *reinterpret_cast<__nv_bfloat162*>(g_WgLo + i)     = l01;
        *reinterpret_cast<__nv_bfloat162*>(g_WgLo + i + 2) = l23;
    }
    {
        float4 v = *reinterpret_cast<const float4*>(Wo + i);
        __nv_bfloat162 h01 = __floats2bfloat162_rn(v.x, v.y);
        __nv_bfloat162 h23 = __floats2bfloat162_rn(v.z, v.w);
        __nv_bfloat162 l01 = __floats2bfloat162_rn(v.x - __low2float(h01),
                                                   v.y - __high2float(h01));
        __nv_bfloat162 l23 = __floats2bfloat162_rn(v.z - __low2float(h23),
                                                   v.w - __high2float(h23));
        *reinterpret_cast<__nv_bfloat162*>(g_WoHi + i)     = h01;
        *reinterpret_cast<__nv_bfloat162*>(g_WoHi + i + 2) = h23;
        *reinterpret_cast<__nv_bfloat162*>(g_WoLo + i)     = l01;
        *reinterpret_cast<__nv_bfloat162*>(g_WoLo + i + 2) = l23;
    }
    if (i < CIN * 64) {  // combined Wk|Wv: row k, col j (j<32 => Wk, else Wv)
        int k = i >> 6, j = i & 63;
        float4 v = (j < 32)
            ? *reinterpret_cast<const float4*>(Wk + k * CH + j)
            : *reinterpret_cast<const float4*>(Wv + k * CH + (j - 32));
        __nv_bfloat162 h01 = __floats2bfloat162_rn(v.x, v.y);
        __nv_bfloat162 h23 = __floats2bfloat162_rn(v.z, v.w);
        __nv_bfloat162 l01 = __floats2bfloat162_rn(v.x - __low2float(h01),
                                                   v.y - __high2float(h01));
        __nv_bfloat162 l23 = __floats2bfloat162_rn(v.z - __low2float(h23),
                                                   v.w - __high2float(h23));
        *reinterpret_cast<__nv_bfloat162*>(g_WkvHi + i)     = h01;
        *reinterpret_cast<__nv_bfloat162*>(g_WkvHi + i + 2) = h23;
        *reinterpret_cast<__nv_bfloat162*>(g_WkvLo + i)     = l01;
        *reinterpret_cast<__nv_bfloat162*>(g_WkvLo + i + 2) = l23;
    }
}

// ---------------------------------------------------------------------------
// mma.sync helpers (bf16x3 split)
// ---------------------------------------------------------------------------
__device__ __forceinline__ void ldsm4(unsigned r[4], unsigned addr) {
    asm volatile("ldmatrix.sync.aligned.m8n8.x4.shared.b16 {%0,%1,%2,%3}, [%4];"
        : "=r"(r[0]), "=r"(r[1]), "=r"(r[2]), "=r"(r[3]) : "r"(addr));
}
__device__ __forceinline__ void ldsm4t(unsigned r[4], unsigned addr) {
    asm volatile("ldmatrix.sync.aligned.m8n8.x4.trans.shared.b16 {%0,%1,%2,%3}, [%4];"
        : "=r"(r[0]), "=r"(r[1]), "=r"(r[2]), "=r"(r[3]) : "r"(addr));
}
__device__ __forceinline__ void mma_bf16(float c[4], const unsigned a[4],
                                         unsigned b0, unsigned b1) {
    asm volatile("mma.sync.aligned.m16n8k16.row.col.f32.bf16.bf16.f32 "
        "{%0,%1,%2,%3}, {%4,%5,%6,%7}, {%8,%9}, {%0,%1,%2,%3};"
        : "+f"(c[0]), "+f"(c[1]), "+f"(c[2]), "+f"(c[3])
        : "r"(a[0]), "r"(a[1]), "r"(a[2]), "r"(a[3]), "r"(b0), "r"(b1));
}
__device__ __forceinline__ void split_store(char* ph, char* pl, float4 v) {
    __nv_bfloat162 h01 = __floats2bfloat162_rn(v.x, v.y);
    __nv_bfloat162 h23 = __floats2bfloat162_rn(v.z, v.w);
    __nv_bfloat162 l01 = __floats2bfloat162_rn(v.x - __low2float(h01),
                                               v.y - __high2float(h01));
    __nv_bfloat162 l23 = __floats2bfloat162_rn(v.z - __low2float(h23),
                                               v.w - __high2float(h23));
    reinterpret_cast<__nv_bfloat162*>(ph)[0] = h01;
    reinterpret_cast<__nv_bfloat162*>(ph)[1] = h23;
    reinterpret_cast<__nv_bfloat162*>(pl)[0] = l01;
    reinterpret_cast<__nv_bfloat162*>(pl)[1] = l23;
}

// ---------------------------------------------------------------------------
// Kernel 2: k|v = m @ (Wk|Wv), bf16x3 + fused masked-mean partials.
// BM=64 (2 CTAs/SM), 256 threads (8 warps in 4x2: 16 rows x 32 cols each).
// Safe cp.async pipeline: wait -> sync -> prefetch(next stage).
// ---------------------------------------------------------------------------
#define KA_STR  264
#define KAH_OFF 0                 // 64 x 264 bf16 = 33792 B
#define KAL_OFF 33792
#define KB_STR  72
#define KB0_OFF 67584             // stage s at KB0 + s*4608; hi then lo (+2304)
#define KV_SMEM 76800

__device__ __forceinline__ void kv_prefetch(unsigned sbase, int stage, int kk, int t) {
    int f = t & 127;
    int row = f >> 3, c8 = (f & 7) << 3;
    unsigned dst = sbase + KB0_OFF + stage * 4608 + ((t < 128) ? 0 : 2304)
                 + (row * KB_STR + c8) * 2;
    const __nv_bfloat16* src = ((t < 128) ? g_WkvHi : g_WkvLo) + (kk + row) * 64 + c8;
    cp16(dst, src);
}

__global__ void __launch_bounds__(256, 2)
kv_kernel(const float* __restrict__ m, const float* __restrict__ mask) {
    extern __shared__ char smc[];
    __shared__ float mask_sm[64];
    unsigned sbase = (unsigned)__cvta_generic_to_shared(smc);
    int t = threadIdx.x;
    int lane = t & 31, wid = t >> 5;
    int wm = wid >> 1, wn = wid & 1;
    int n    = blockIdx.x >> 4;
    int tile = blockIdx.x & 15;
    long r0g = (long)blockIdx.x * 64;

    if (t < 64) mask_sm[t] = mask[(size_t)n * SLEN + tile * 64 + t];

    // load m tile [64][256] fp32, split into hi/lo smem
    #pragma unroll
    for (int i = 0; i < 16; i++) {
        int idx = t + i * 256;
        int row = idx >> 6;
        int c4  = (idx & 63) << 2;
        float4 v = *reinterpret_cast<const float4*>(m + (r0g + row) * CIN + c4);
        split_store(smc + KAH_OFF + (row * KA_STR + c4) * 2,
                    smc + KAL_OFF + (row * KA_STR + c4) * 2, v);
    }
    __syncthreads();

    kv_prefetch(sbase, 0, 0, t);
    CP_COMMIT();

    // masked-mean partial for channel t over this CTA's 64 tokens
    {
        float qs = 0.f;
        #pragma unroll 8
        for (int r = 0; r < 64; r++) {
            float hi = __bfloat162float(*reinterpret_cast<__nv_bfloat16*>(
                smc + KAH_OFF + (r * KA_STR + t) * 2));
            float lo = __bfloat162float(*reinterpret_cast<__nv_bfloat16*>(
                smc + KAL_OFF + (r * KA_STR + t) * 2));
            qs = fmaf(hi + lo, mask_sm[r], qs);
        }
        g_qpart[(tile * NROWS + n) * CIN + t] = qs;
        if (t == 0) {
            float ms = 0.f;
            for (int r = 0; r < 64; r++) ms += mask_sm[r];
            g_mpart[tile * NROWS + n] = ms;
        }
    }

    float acc[4][4];
    #pragma unroll
    for (int i = 0; i < 4; i++)
        #pragma unroll
        for (int j = 0; j < 4; j++) acc[i][j] = 0.f;

    for (int c = 0; c < 16; c++) {
        CP_WAIT0();
        __syncthreads();
        if (c < 15) { kv_prefetch(sbase, (c + 1) & 1, (c + 1) * 16, t); CP_COMMIT(); }
        int kk = c * 16;
        unsigned kbh = sbase + KB0_OFF + (c & 1) * 4608;

        unsigned ah[4], al[4];
        unsigned aaddr = sbase + KAH_OFF +
            ((wm * 16 + (lane & 15)) * KA_STR + kk + ((lane >> 4) << 3)) * 2;
        ldsm4(ah, aaddr);
        ldsm4(al, aaddr + KAL_OFF);

        #pragma unroll
        for (int nb = 0; nb < 2; nb++) {
            int col0 = wn * 32 + nb * 16;
            unsigned baddr = kbh +
                ((lane & 15) * KB_STR + col0 + ((lane >> 4) << 3)) * 2;
            unsigned bh[4], bl[4];
            ldsm4t(bh, baddr);
            ldsm4t(bl, baddr + 2304);
            mma_bf16(acc[nb * 2],     ah, bh[0], bh[1]);
            mma_bf16(acc[nb * 2],     ah, bl[0], bl[1]);
            mma_bf16(acc[nb * 2],     al, bh[0], bh[1]);
            mma_bf16(acc[nb * 2 + 1], ah, bh[2], bh[3]);
            mma_bf16(acc[nb * 2 + 1], ah, bl[2], bl[3]);
            mma_bf16(acc[nb * 2 + 1], al, bh[2], bh[3]);
        }
    }

    // write k (cols 0..31) and v (cols 32..63)
    #pragma unroll
    for (int nb = 0; nb < 2; nb++) {
        #pragma unroll
        for (int half = 0; half < 2; half++) {
            int col = wn * 32 + nb * 16 + half * 8 + (lane & 3) * 2;
            int r0  = wm * 16 + (lane >> 2);
            float* f = acc[nb * 2 + half];
            float* dst = (col < CH) ? (g_k_buf + ((r0g + r0) * CH + col))
                                    : (g_v_buf + ((r0g + r0) * CH + col - CH));
            *reinterpret_cast<float2*>(dst) = make_float2(f[0], f[1]);
            dst += 8 * CH;
            *reinterpret_cast<float2*>(dst) = make_float2(f[2], f[3]);
        }
    }
}

// ---------------------------------------------------------------------------
// Kernel 2b: finish mean + q = (mean @ Wq) * C^-0.5
// ---------------------------------------------------------------------------
__global__ void q2_kernel(const float* __restrict__ Wq) {
    int n = blockIdx.x, t = threadIdx.x;
    __shared__ float qm[CIN];
    float s = 0.f;
    #pragma unroll
    for (int p = 0; p < 16; p++) s += g_qpart[(p * NROWS + n) * CIN + t];
    float mk = 0.f;
    #pragma unroll
    for (int p = 0; p < 16; p++) mk += g_mpart[p * NROWS + n];
    qm[t] = s / (mk + 1e-10f);
    __syncthreads();
    float acc = 0.f;
    #pragma unroll 8
    for (int c = 0; c < CIN; c++) acc = fmaf(qm[c], Wq[c * HC + t], acc);
    g_q_buf[n * HC + t] = acc * 0.17677669529663687f;
}

// ---------------------------------------------------------------------------
// Kernel 3a: split-S attention partials. grid (384, 2); each CTA handles 512
// sequence positions: logits, per-head partial max/sum, unnormalized p@v.
// ---------------------------------------------------------------------------
#define S2 512

__global__ void __launch_bounds__(256)
attn_part_kernel(const float* __restrict__ mask) {
    int n = blockIdx.x, half = blockIdx.y, t = threadIdx.x;
    int s0 = half * S2;
    __shared__ float q_sm[HC];
    __shared__ float p_sm[NH * S2];   // 16 KB

    q_sm[t] = g_q_buf[n * HC + t];
    __syncthreads();

    const float* krow = g_k_buf + ((size_t)n * SLEN + s0) * CH;
    const float* vrow = g_v_buf + ((size_t)n * SLEN + s0) * CH;
    const float* mk   = mask + (size_t)n * SLEN + s0;

    #pragma unroll
    for (int i = 0; i < 2; i++) {
        int s = t + i * 256;
        float kreg[32];
        #pragma unroll
        for (int q = 0; q < 8; q++)
            *reinterpret_cast<float4*>(kreg + q * 4) =
                *reinterpret_cast<const float4*>(krow + (size_t)s * CH + q * 4);
        float bias = 1e9f * (mk[s] - 1.0f);
        #pragma unroll
        for (int h = 0; h < NH; h++) {
            float d = 0.f;
            #pragma unroll
            for (int j = 0; j < 32; j++) d = fmaf(q_sm[h * 32 + j], kreg[j], d);
            p_sm[h * S2 + s] = d + bias;
        }
    }
    __syncthreads();

    int h = t >> 5, lane = t & 31;
    float mx = -3.0e38f;
    for (int s = lane; s < S2; s += 32) mx = fmaxf(mx, p_sm[h * S2 + s]);
    #pragma unroll
    for (int off = 16; off > 0; off >>= 1)
        mx = fmaxf(mx, __shfl_xor_sync(0xffffffffu, mx, off));

    float sum = 0.f;
    for (int s = lane; s < S2; s += 32) {
        float e = __expf(p_sm[h * S2 + s] - mx);
        p_sm[h * S2 + s] = e;
        sum += e;
    }
    #pragma unroll
    for (int off = 16; off > 0; off >>= 1)
        sum += __shfl_xor_sync(0xffffffffu, sum, off);
    if (lane == 0) {
        g_stat[((half * NROWS + n) * NH + h) * 2]     = mx;
        g_stat[((half * NROWS + n) * NH + h) * 2 + 1] = sum;
    }
    __syncthreads();

    // unnormalized p@v partial
    {
        int sg  = lane >> 3;
        int c4  = (lane & 7) << 2;
        float4 acc4 = make_float4(0.f, 0.f, 0.f, 0.f);
        const float* ph = p_sm + h * S2;
        #pragma unroll 4
        for (int s = sg; s < S2; s += 4) {
            float p = ph[s];
            float4 v4 = *reinterpret_cast<const float4*>(vrow + (size_t)s * CH + c4);
            acc4.x = fmaf(p, v4.x, acc4.x);
            acc4.y = fmaf(p, v4.y, acc4.y);
            acc4.z = fmaf(p, v4.z, acc4.z);
            acc4.w = fmaf(p, v4.w, acc4.w);
        }
        #pragma unroll
        for (int off = 8; off <= 16; off <<= 1) {
            acc4.x += __shfl_xor_sync(0xffffffffu, acc4.x, off);
            acc4.y += __shfl_xor_sync(0xffffffffu, acc4.y, off);
            acc4.z += __shfl_xor_sync(0xffffffffu, acc4.z, off);
            acc4.w += __shfl_xor_sync(0xffffffffu, acc4.w, off);
        }
        if (sg == 0)
            *reinterpret_cast<float4*>(
                g_opart + (half * NROWS + n) * HC + h * CH + c4) = acc4;
    }
}

// ---------------------------------------------------------------------------
// Kernel 3b: merge the two S-halves: o = (w1*o1 + w2*o2) / (w1*s1 + w2*s2)
// ---------------------------------------------------------------------------
__global__ void attn_merge_kernel() {
    int n = blockIdx.x, t = threadIdx.x;
    int h = t >> 5;
    float m1 = g_stat[((0 * NROWS + n) * NH + h) * 2];
    float s1 = g_stat[((0 * NROWS + n) * NH + h) * 2 + 1];
    float m2 = g_stat[((1 * NROWS + n) * NH + h) * 2];
    float s2 = g_stat[((1 * NROWS + n) * NH + h) * 2 + 1];
    float M  = fmaxf(m1, m2);
    float w1 = __expf(m1 - M), w2 = __expf(m2 - M);
    float o1 = g_opart[(0 * NROWS + n) * HC + t];
    float o2 = g_opart[(1 * NROWS + n) * HC + t];
    g_o_buf[n * HC + t] = (w1 * o1 + w2 * o2) / (w1 * s1 + w2 * s2);
}

// ---------------------------------------------------------------------------
// Kernel 4: out_kernel (mma.sync bf16x3), BM=64, 256 threads, 2 CTAs/SM.
// Safe cp.async pipeline + cross-GEMM first-chunk prefetch overlap.
// ---------------------------------------------------------------------------
#define A_STR   264
#define AH_OFF  0                 // 64 x 264 bf16 = 33792 B
#define AL_OFF  33792
#define B0_OFF  67584             // stage s at B0 + s*16896; hi then lo (+8448)
#define BG_OFF  101376
#define OV_OFF  102400
#define BO_OFF  103424
#define SMEM_BYTES 104448

__device__ __forceinline__ void out_prefetch(unsigned sbase, int stage,
        const __nv_bfloat16* __restrict__ WHi,
        const __nv_bfloat16* __restrict__ WLo, int kk, int t) {
    unsigned bh = sbase + B0_OFF + stage * 16896;
    #pragma unroll
    for (int i = 0; i < 2; i++) {
        int f = t + i * 256;
        int row = f >> 5, c8 = (f & 31) << 3;
        unsigned off = (row * A_STR + c8) * 2;
        cp16(bh + off,        WHi + (kk + row) * 256 + c8);
        cp16(bh + 8448 + off, WLo + (kk + row) * 256 + c8);
    }
}

// One 64x256 GEMM; if pre0, chunk 0 was already prefetched+committed by the
// caller.  At the last chunk, prefetch WnHi/WnLo chunk 0 (next GEMM) so the
// epilogue overlaps that load.
__device__ __forceinline__ void gemm_bf16x3(
    unsigned sbase,
    const __nv_bfloat16* __restrict__ WHi,
    const __nv_bfloat16* __restrict__ WLo,
    float acc[16][4], int t, int lane, int wm, int wn, bool pre0,
    const __nv_bfloat16* __restrict__ WnHi,
    const __nv_bfloat16* __restrict__ WnLo)
{
    if (!pre0) { out_prefetch(sbase, 0, WHi, WLo, 0, t); CP_COMMIT(); }
    for (int c = 0; c < 16; c++) {
        CP_WAIT0();
        __syncthreads();
        if (c < 15)      { out_prefetch(sbase, (c + 1) & 1, WHi, WLo, (c + 1) * 16, t); CP_COMMIT(); }
        else if (WnHi)   { out_prefetch(sbase, 0, WnHi, WnLo, 0, t); CP_COMMIT(); }
        int kk = c * 16;
        unsigned bhb = sbase + B0_OFF + (c & 1) * 16896;

        unsigned ah[4], al[4];
        unsigned aaddr = sbase + AH_OFF +
            ((wm * 16 + (lane & 15)) * A_STR + kk + ((lane >> 4) << 3)) * 2;
        ldsm4(ah, aaddr);
        ldsm4(al, aaddr + AL_OFF);

        #pragma unroll
        for (int nb = 0; nb < 8; nb++) {
            int n0 = wn * 128 + nb * 16;
            unsigned baddr = bhb +
                ((lane & 15) * A_STR + n0 + ((lane >> 4) << 3)) * 2;
            unsigned bh4[4], bl4[4];
            ldsm4t(bh4, baddr);
            ldsm4t(bl4, baddr + 8448);
            mma_bf16(acc[nb * 2],     ah, bh4[0], bh4[1]);
            mma_bf16(acc[nb * 2],     ah, bl4[0], bl4[1]);
            mma_bf16(acc[nb * 2],     al, bh4[0], bh4[1]);
            mma_bf16(acc[nb * 2 + 1], ah, bh4[2], bh4[3]);
            mma_bf16(acc[nb * 2 + 1], ah, bl4[2], bl4[3]);
            mma_bf16(acc[nb * 2 + 1], al, bh4[2], bh4[3]);
        }
    }
    __syncthreads();   // protect A smem: epilogue rewrites it next
}

__global__ void __launch_bounds__(256, 2)
out_kernel(const float* __restrict__ m,
           const float* __restrict__ bg,
           const float* __restrict__ bo,
           float* __restrict__ out) {
    extern __shared__ char smc[];
    unsigned sbase = (unsigned)__cvta_generic_to_shared(smc);
    float* sBG = reinterpret_cast<float*>(smc + BG_OFF);
    float* sOV = reinterpret_cast<float*>(smc + OV_OFF);
    float* sBO = reinterpret_cast<float*>(smc + BO_OFF);

    int t = threadIdx.x;
    int lane = t & 31, wid = t >> 5;
    int wm = wid >> 1, wn = wid & 1;
    int n = blockIdx.y;
    long tok0 = (long)n * SLEN + (long)blockIdx.x * 64;

    sBG[t] = bg[t];
    sOV[t] = g_o_buf[n * HC + t];
    sBO[t] = bo[t];

    // load m tile [64][256] fp32 once, split into bf16 hi/lo smem
    #pragma unroll
    for (int i = 0; i < 16; i++) {
        int idx = t + i * 256;
        int row = idx >> 6;
        int c4  = (idx & 63) << 2;
        float4 v = *reinterpret_cast<const float4*>(m + (tok0 + row) * CIN + c4);
        split_store(smc + AH_OFF + (row * A_STR + c4) * 2,
                    smc + AL_OFF + (row * A_STR + c4) * 2, v);
    }
    __syncthreads();

    float acc[16][4];
    #pragma unroll
    for (int i = 0; i < 16; i++)
        #pragma unroll
        for (int j = 0; j < 4; j++) acc[i][j] = 0.f;

    // ---- GEMM1: M @ Wg (prefetches Wo chunk 0 at its tail) ----
    gemm_bf16x3(sbase, g_WgHi, g_WgLo, acc, t, lane, wm, wn,
                false, g_WoHi, g_WoLo);

    // ---- epilogue 1: G = ov * sigmoid(acc + bg), split back into Ah/Al ----
    #pragma unroll
    for (int nt = 0; nt < 16; nt++) {
        int col0 = wn * 128 + nt * 8 + (lane & 3) * 2;
        int r0   = wm * 16 + (lane >> 2);
        float bg0 = sBG[col0], bg1 = sBG[col0 + 1];
        float ov0 = sOV[col0], ov1 = sOV[col0 + 1];
        float g0 = ov0 / (1.f + __expf(-(acc[nt][0] + bg0)));
        float g1 = ov1 / (1.f + __expf(-(acc[nt][1] + bg1)));
        float g2 = ov0 / (1.f + __expf(-(acc[nt][2] + bg0)));
        float g3 = ov1 / (1.f + __expf(-(acc[nt][3] + bg1)));
        __nv_bfloat162 h01 = __floats2bfloat162_rn(g0, g1);
        __nv_bfloat162 l01 = __floats2bfloat162_rn(g0 - __low2float(h01),
                                                   g1 - __high2float(h01));
        __nv_bfloat162 h23 = __floats2bfloat162_rn(g2, g3);
        __nv_bfloat162 l23 = __floats2bfloat162_rn(g2 - __low2float(h23),
                                                   g3 - __high2float(h23));
        *reinterpret_cast<__nv_bfloat162*>(smc + AH_OFF + (r0 * A_STR + col0) * 2)       = h01;
        *reinterpret_cast<__nv_bfloat162*>(smc + AL_OFF + (r0 * A_STR + col0) * 2)       = l01;
        *reinterpret_cast<__nv_bfloat162*>(smc + AH_OFF + ((r0 + 8) * A_STR + col0) * 2) = h23;
        *reinterpret_cast<__nv_bfloat162*>(smc + AL_OFF + ((r0 + 8) * A_STR + col0) * 2) = l23;
        acc[nt][0] = acc[nt][1] = acc[nt][2] = acc[nt][3] = 0.f;
    }
    __syncthreads();

    // ---- GEMM2: G @ Wo (chunk 0 already in flight) ----
    gemm_bf16x3(sbase, g_WoHi, g_WoLo, acc, t, lane, wm, wn,
                true, (const __nv_bfloat16*)0, (const __nv_bfloat16*)0);

    // ---- epilogue 2: + bo, write out ----
    #pragma unroll
    for (int nt = 0; nt < 16; nt++) {
        int col0 = wn * 128 + nt * 8 + (lane & 3) * 2;
        int r0   = wm * 16 + (lane >> 2);
        float2 o0 = make_float2(acc[nt][0] + sBO[col0], acc[nt][1] + sBO[col0 + 1]);
        float2 o1 = make_float2(acc[nt][2] + sBO[col0], acc[nt][3] + sBO[col0 + 1]);
        *reinterpret_cast<float2*>(out + (tok0 + r0) * CIN + col0)     = o0;
        *reinterpret_cast<float2*>(out + (tok0 + r0 + 8) * CIN + col0) = o1;
    }
}

// ---------------------------------------------------------------------------
extern "C" void kernel_launch(void* const* d_in, const int* in_sizes, int n_in,
                              void* d_out, int out_size) {
    const float* m    = (const float*)d_in[0];
    const float* mask = (const float*)d_in[1];
    const float* Wq   = (const float*)d_in[2];
    const float* Wk   = (const float*)d_in[3];
    const float* Wv   = (const float*)d_in[4];
    const float* Wg   = (const float*)d_in[5];
    const float* bg   = (const float*)d_in[6];
    const float* Wo   = (const float*)d_in[7];
    const float* bo   = (const float*)d_in[8];
    float* out = (float*)d_out;

    wconv_kernel<<<64, 256>>>(Wg, Wo, Wk, Wv);

    cudaFuncSetAttribute(kv_kernel,
                         cudaFuncAttributeMaxDynamicSharedMemorySize, KV_SMEM);
    kv_kernel<<<(NROWS * SLEN) / 64, 256, KV_SMEM>>>(m, mask);

    q2_kernel<<<NROWS, 256>>>(Wq);

    attn_part_kernel<<<dim3(NROWS, 2), 256>>>(mask);
    attn_merge_kernel<<<NROWS, 256>>>();

    cudaFuncSetAttribute(out_kernel,
                         cudaFuncAttributeMaxDynamicSharedMemorySize, SMEM_BYTES);
    out_kernel<<<dim3(SLEN / 64, NROWS), 256, SMEM_BYTES>>>(m, bg, bo, out);
}

// round 12
// speedup vs baseline: 1.3044x; 1.1831x over previous
#include <cuda_runtime.h>
#include <cuda_bf16.h>
#include <cuda_fp16.h>
#include <math.h>

#define NROWS 384
#define SLEN  1024
#define CIN   256
#define CH    32
#define NH    8
#define HC    256   // NH*CH

// Scratch (no cudaMalloc allowed).
__device__ float g_q_buf[NROWS * HC];
__device__ float g_o_buf[NROWS * HC];
__device__ float g_k_buf[(size_t)NROWS * SLEN * CH];
__device__ float g_v_buf[(size_t)NROWS * SLEN * CH];
// Pre-split weights. Wg: single fp16 (feeds sigmoid; error damped 4x).
// Wo: bf16 hi/lo (full precision path). Wk|Wv: bf16 hi/lo.
__device__ __half        g_Wg16[CIN * HC];
__device__ __nv_bfloat16 g_WoHi[HC * CIN], g_WoLo[HC * CIN];
__device__ __nv_bfloat16 g_WkvHi[CIN * 64], g_WkvLo[CIN * 64];
// Masked-mean partials: [tile 0..15][n][c] and [tile][n]
__device__ float g_qpart[16 * NROWS * CIN];
__device__ float g_mpart[16 * NROWS];
// Split-S attention partials: [quarter][n][hc] and stats [quarter][n][h][2]
__device__ float g_opart[4 * NROWS * HC];
__device__ float g_stat[4 * NROWS * NH * 2];

// ---------------------------------------------------------------------------
// cp.async helpers
// ---------------------------------------------------------------------------
__device__ __forceinline__ void cp16(unsigned saddr, const void* g) {
    asm volatile("cp.async.cg.shared.global [%0], [%1], 16;" :: "r"(saddr), "l"(g));
}
#define CP_COMMIT() asm volatile("cp.async.commit_group;" ::: "memory")
#define CP_WAIT0()  asm volatile("cp.async.wait_group 0;" ::: "memory")

// ---------------------------------------------------------------------------
// Kernel 0: weight conversion (Wg->fp16, Wo->bf16 hi/lo, Wk|Wv->bf16 hi/lo)
// ---------------------------------------------------------------------------
__global__ void wconv_kernel(const float* __restrict__ Wg,
                             const float* __restrict__ Wo,
                             const float* __restrict__ Wk,
                             const float* __restrict__ Wv) {
    int i = (blockIdx.x * 256 + threadIdx.x) * 4;  // 65536 elems per big matrix
    {
        float4 v = *reinterpret_cast<const float4*>(Wg + i);
        __half2 a = __floats2half2_rn(v.x, v.y);
        __half2 b = __floats2half2_rn(v.z, v.w);
        *reinterpret_cast<__half2*>(g_Wg16 + i)     = a;
        *reinterpret_cast<__half2*>(g_Wg16 + i + 2) = b;
    }
    {
        float4 v = *reinterpret_cast<const float4*>(Wo + i);
        __nv_bfloat162 h01 = __floats2bfloat162_rn(v.x, v.y);
        __nv_bfloat162 h23 = __floats2bfloat162_rn(v.z, v.w);
        __nv_bfloat162 l01 = __floats2bfloat162_rn(v.x - __low2float(h01),
                                                   v.y - __high2float(h01));
        __nv_bfloat162 l23 = __floats2bfloat162_rn(v.z - __low2float(h23),
                                                   v.w - __high2float(h23));
        *reinterpret_cast<__nv_bfloat162*>(g_WoHi + i)     = h01;
        *reinterpret_cast<__nv_bfloat162*>(g_WoHi + i + 2) = h23;
        *reinterpret_cast<__nv_bfloat162*>(g_WoLo + i)     = l01;
        *reinterpret_cast<__nv_bfloat162*>(g_WoLo + i + 2) = l23;
    }
    if (i < CIN * 64) {  // combined Wk|Wv: row k, col j (j<32 => Wk, else Wv)
        int k = i >> 6, j = i & 63;
        float4 v = (j < 32)
            ? *reinterpret_cast<const float4*>(Wk + k * CH + j)
            : *reinterpret_cast<const float4*>(Wv + k * CH + (j - 32));
        __nv_bfloat162 h01 = __floats2bfloat162_rn(v.x, v.y);
        __nv_bfloat162 h23 = __floats2bfloat162_rn(v.z, v.w);
        __nv_bfloat162 l01 = __floats2bfloat162_rn(v.x - __low2float(h01),
                                                   v.y - __high2float(h01));
        __nv_bfloat162 l23 = __floats2bfloat162_rn(v.z - __low2float(h23),
                                                   v.w - __high2float(h23));
        *reinterpret_cast<__nv_bfloat162*>(g_WkvHi + i)     = h01;
        *reinterpret_cast<__nv_bfloat162*>(g_WkvHi + i + 2) = h23;
        *reinterpret_cast<__nv_bfloat162*>(g_WkvLo + i)     = l01;
        *reinterpret_cast<__nv_bfloat162*>(g_WkvLo + i + 2) = l23;
    }
}

// ---------------------------------------------------------------------------
// mma helpers
// ---------------------------------------------------------------------------
__device__ __forceinline__ void ldsm4(unsigned r[4], unsigned addr) {
    asm volatile("ldmatrix.sync.aligned.m8n8.x4.shared.b16 {%0,%1,%2,%3}, [%4];"
        : "=r"(r[0]), "=r"(r[1]), "=r"(r[2]), "=r"(r[3]) : "r"(addr));
}
__device__ __forceinline__ void ldsm4t(unsigned r[4], unsigned addr) {
    asm volatile("ldmatrix.sync.aligned.m8n8.x4.trans.shared.b16 {%0,%1,%2,%3}, [%4];"
        : "=r"(r[0]), "=r"(r[1]), "=r"(r[2]), "=r"(r[3]) : "r"(addr));
}
__device__ __forceinline__ void mma_bf16(float c[4], const unsigned a[4],
                                         unsigned b0, unsigned b1) {
    asm volatile("mma.sync.aligned.m16n8k16.row.col.f32.bf16.bf16.f32 "
        "{%0,%1,%2,%3}, {%4,%5,%6,%7}, {%8,%9}, {%0,%1,%2,%3};"
        : "+f"(c[0]), "+f"(c[1]), "+f"(c[2]), "+f"(c[3])
        : "r"(a[0]), "r"(a[1]), "r"(a[2]), "r"(a[3]), "r"(b0), "r"(b1));
}
__device__ __forceinline__ void mma_fp16(float c[4], const unsigned a[4],
                                         unsigned b0, unsigned b1) {
    asm volatile("mma.sync.aligned.m16n8k16.row.col.f32.f16.f16.f32 "
        "{%0,%1,%2,%3}, {%4,%5,%6,%7}, {%8,%9}, {%0,%1,%2,%3};"
        : "+f"(c[0]), "+f"(c[1]), "+f"(c[2]), "+f"(c[3])
        : "r"(a[0]), "r"(a[1]), "r"(a[2]), "r"(a[3]), "r"(b0), "r"(b1));
}
__device__ __forceinline__ void split_store(char* ph, char* pl, float4 v) {
    __nv_bfloat162 h01 = __floats2bfloat162_rn(v.x, v.y);
    __nv_bfloat162 h23 = __floats2bfloat162_rn(v.z, v.w);
    __nv_bfloat162 l01 = __floats2bfloat162_rn(v.x - __low2float(h01),
                                               v.y - __high2float(h01));
    __nv_bfloat162 l23 = __floats2bfloat162_rn(v.z - __low2float(h23),
                                               v.w - __high2float(h23));
    reinterpret_cast<__nv_bfloat162*>(ph)[0] = h01;
    reinterpret_cast<__nv_bfloat162*>(ph)[1] = h23;
    reinterpret_cast<__nv_bfloat162*>(pl)[0] = l01;
    reinterpret_cast<__nv_bfloat162*>(pl)[1] = l23;
}

// ---------------------------------------------------------------------------
// Kernel 2: k|v = m @ (Wk|Wv), bf16x3 + fused masked-mean partials (R11, kept)
// ---------------------------------------------------------------------------
#define KA_STR  264
#define KAH_OFF 0
#define KAL_OFF 33792
#define KB_STR  72
#define KB0_OFF 67584
#define KV_SMEM 76800

__device__ __forceinline__ void kv_prefetch(unsigned sbase, int stage, int kk, int t) {
    int f = t & 127;
    int row = f >> 3, c8 = (f & 7) << 3;
    unsigned dst = sbase + KB0_OFF + stage * 4608 + ((t < 128) ? 0 : 2304)
                 + (row * KB_STR + c8) * 2;
    const __nv_bfloat16* src = ((t < 128) ? g_WkvHi : g_WkvLo) + (kk + row) * 64 + c8;
    cp16(dst, src);
}

__global__ void __launch_bounds__(256, 2)
kv_kernel(const float* __restrict__ m, const float* __restrict__ mask) {
    extern __shared__ char smc[];
    __shared__ float mask_sm[64];
    unsigned sbase = (unsigned)__cvta_generic_to_shared(smc);
    int t = threadIdx.x;
    int lane = t & 31, wid = t >> 5;
    int wm = wid >> 1, wn = wid & 1;
    int n    = blockIdx.x >> 4;
    int tile = blockIdx.x & 15;
    long r0g = (long)blockIdx.x * 64;

    if (t < 64) mask_sm[t] = mask[(size_t)n * SLEN + tile * 64 + t];

    #pragma unroll
    for (int i = 0; i < 16; i++) {
        int idx = t + i * 256;
        int row = idx >> 6;
        int c4  = (idx & 63) << 2;
        float4 v = *reinterpret_cast<const float4*>(m + (r0g + row) * CIN + c4);
        split_store(smc + KAH_OFF + (row * KA_STR + c4) * 2,
                    smc + KAL_OFF + (row * KA_STR + c4) * 2, v);
    }
    __syncthreads();

    kv_prefetch(sbase, 0, 0, t);
    CP_COMMIT();

    {
        float qs = 0.f;
        #pragma unroll 8
        for (int r = 0; r < 64; r++) {
            float hi = __bfloat162float(*reinterpret_cast<__nv_bfloat16*>(
                smc + KAH_OFF + (r * KA_STR + t) * 2));
            float lo = __bfloat162float(*reinterpret_cast<__nv_bfloat16*>(
                smc + KAL_OFF + (r * KA_STR + t) * 2));
            qs = fmaf(hi + lo, mask_sm[r], qs);
        }
        g_qpart[(tile * NROWS + n) * CIN + t] = qs;
        if (t == 0) {
            float ms = 0.f;
            for (int r = 0; r < 64; r++) ms += mask_sm[r];
            g_mpart[tile * NROWS + n] = ms;
        }
    }

    float acc[4][4];
    #pragma unroll
    for (int i = 0; i < 4; i++)
        #pragma unroll
        for (int j = 0; j < 4; j++) acc[i][j] = 0.f;

    for (int c = 0; c < 16; c++) {
        CP_WAIT0();
        __syncthreads();
        if (c < 15) { kv_prefetch(sbase, (c + 1) & 1, (c + 1) * 16, t); CP_COMMIT(); }
        int kk = c * 16;
        unsigned kbh = sbase + KB0_OFF + (c & 1) * 4608;

        unsigned ah[4], al[4];
        unsigned aaddr = sbase + KAH_OFF +
            ((wm * 16 + (lane & 15)) * KA_STR + kk + ((lane >> 4) << 3)) * 2;
        ldsm4(ah, aaddr);
        ldsm4(al, aaddr + KAL_OFF);

        #pragma unroll
        for (int nb = 0; nb < 2; nb++) {
            int col0 = wn * 32 + nb * 16;
            unsigned baddr = kbh +
                ((lane & 15) * KB_STR + col0 + ((lane >> 4) << 3)) * 2;
            unsigned bh[4], bl[4];
            ldsm4t(bh, baddr);
            ldsm4t(bl, baddr + 2304);
            mma_bf16(acc[nb * 2],     ah, bh[0], bh[1]);
            mma_bf16(acc[nb * 2],     ah, bl[0], bl[1]);
            mma_bf16(acc[nb * 2],     al, bh[0], bh[1]);
            mma_bf16(acc[nb * 2 + 1], ah, bh[2], bh[3]);
            mma_bf16(acc[nb * 2 + 1], ah, bl[2], bl[3]);
            mma_bf16(acc[nb * 2 + 1], al, bh[2], bh[3]);
        }
    }

    #pragma unroll
    for (int nb = 0; nb < 2; nb++) {
        #pragma unroll
        for (int half = 0; half < 2; half++) {
            int col = wn * 32 + nb * 16 + half * 8 + (lane & 3) * 2;
            int r0  = wm * 16 + (lane >> 2);
            float* f = acc[nb * 2 + half];
            float* dst = (col < CH) ? (g_k_buf + ((r0g + r0) * CH + col))
                                    : (g_v_buf + ((r0g + r0) * CH + col - CH));
            *reinterpret_cast<float2*>(dst) = make_float2(f[0], f[1]);
            dst += 8 * CH;
            *reinterpret_cast<float2*>(dst) = make_float2(f[2], f[3]);
        }
    }
}

// ---------------------------------------------------------------------------
// Kernel 2b: finish mean + q = (mean @ Wq) * C^-0.5
// ---------------------------------------------------------------------------
__global__ void q2_kernel(const float* __restrict__ Wq) {
    int n = blockIdx.x, t = threadIdx.x;
    __shared__ float qm[CIN];
    float s = 0.f;
    #pragma unroll
    for (int p = 0; p < 16; p++) s += g_qpart[(p * NROWS + n) * CIN + t];
    float mk = 0.f;
    #pragma unroll
    for (int p = 0; p < 16; p++) mk += g_mpart[p * NROWS + n];
    qm[t] = s / (mk + 1e-10f);
    __syncthreads();
    float acc = 0.f;
    #pragma unroll 8
    for (int c = 0; c < CIN; c++) acc = fmaf(qm[c], Wq[c * HC + t], acc);
    g_q_buf[n * HC + t] = acc * 0.17677669529663687f;
}

// ---------------------------------------------------------------------------
// Kernel 3a: split-S attention partials, 4 quarters. grid (384, 4).
// ---------------------------------------------------------------------------
#define S4 256

__global__ void __launch_bounds__(256)
attn_part_kernel(const float* __restrict__ mask) {
    int n = blockIdx.x, qt = blockIdx.y, t = threadIdx.x;
    int s0 = qt * S4;
    __shared__ float q_sm[HC];
    __shared__ float p_sm[NH * S4];   // 8 KB

    q_sm[t] = g_q_buf[n * HC + t];
    __syncthreads();

    const float* krow = g_k_buf + ((size_t)n * SLEN + s0) * CH;
    const float* vrow = g_v_buf + ((size_t)n * SLEN + s0) * CH;
    const float* mk   = mask + (size_t)n * SLEN + s0;

    {
        int s = t;
        float kreg[32];
        #pragma unroll
        for (int q = 0; q < 8; q++)
            *reinterpret_cast<float4*>(kreg + q * 4) =
                *reinterpret_cast<const float4*>(krow + (size_t)s * CH + q * 4);
        float bias = 1e9f * (mk[s] - 1.0f);
        #pragma unroll
        for (int h = 0; h < NH; h++) {
            float d = 0.f;
            #pragma unroll
            for (int j = 0; j < 32; j++) d = fmaf(q_sm[h * 32 + j], kreg[j], d);
            p_sm[h * S4 + s] = d + bias;
        }
    }
    __syncthreads();

    int h = t >> 5, lane = t & 31;
    float mx = -3.0e38f;
    for (int s = lane; s < S4; s += 32) mx = fmaxf(mx, p_sm[h * S4 + s]);
    #pragma unroll
    for (int off = 16; off > 0; off >>= 1)
        mx = fmaxf(mx, __shfl_xor_sync(0xffffffffu, mx, off));

    float sum = 0.f;
    for (int s = lane; s < S4; s += 32) {
        float e = __expf(p_sm[h * S4 + s] - mx);
        p_sm[h * S4 + s] = e;
        sum += e;
    }
    #pragma unroll
    for (int off = 16; off > 0; off >>= 1)
        sum += __shfl_xor_sync(0xffffffffu, sum, off);
    if (lane == 0) {
        g_stat[((qt * NROWS + n) * NH + h) * 2]     = mx;
        g_stat[((qt * NROWS + n) * NH + h) * 2 + 1] = sum;
    }
    __syncthreads();

    // unnormalized p@v partial
    {
        int sg  = lane >> 3;
        int c4  = (lane & 7) << 2;
        float4 acc4 = make_float4(0.f, 0.f, 0.f, 0.f);
        const float* ph = p_sm + h * S4;
        #pragma unroll 4
        for (int s = sg; s < S4; s += 4) {
            float p = ph[s];
            float4 v4 = *reinterpret_cast<const float4*>(vrow + (size_t)s * CH + c4);
            acc4.x = fmaf(p, v4.x, acc4.x);
            acc4.y = fmaf(p, v4.y, acc4.y);
            acc4.z = fmaf(p, v4.z, acc4.z);
            acc4.w = fmaf(p, v4.w, acc4.w);
        }
        #pragma unroll
        for (int off = 8; off <= 16; off <<= 1) {
            acc4.x += __shfl_xor_sync(0xffffffffu, acc4.x, off);
            acc4.y += __shfl_xor_sync(0xffffffffu, acc4.y, off);
            acc4.z += __shfl_xor_sync(0xffffffffu, acc4.z, off);
            acc4.w += __shfl_xor_sync(0xffffffffu, acc4.w, off);
        }
        if (sg == 0)
            *reinterpret_cast<float4*>(
                g_opart + (qt * NROWS + n) * HC + h * CH + c4) = acc4;
    }
}

// ---------------------------------------------------------------------------
// Kernel 3b: merge the four S-quarters
// ---------------------------------------------------------------------------
__global__ void attn_merge_kernel() {
    int n = blockIdx.x, t = threadIdx.x;
    int h = t >> 5;
    float mq[4], sq[4];
    #pragma unroll
    for (int p = 0; p < 4; p++) {
        mq[p] = g_stat[((p * NROWS + n) * NH + h) * 2];
        sq[p] = g_stat[((p * NROWS + n) * NH + h) * 2 + 1];
    }
    float M = fmaxf(fmaxf(mq[0], mq[1]), fmaxf(mq[2], mq[3]));
    float num = 0.f, den = 0.f;
    #pragma unroll
    for (int p = 0; p < 4; p++) {
        float w = __expf(mq[p] - M);
        num = fmaf(w, g_opart[(p * NROWS + n) * HC + t], num);
        den = fmaf(w, sq[p], den);
    }
    g_o_buf[n * HC + t] = num / den;
}

// ---------------------------------------------------------------------------
// Kernel 4: out_kernel.  GEMM1 = fp16 single-MMA (sigmoid-damped error),
// GEMM2 = bf16x3.  BM=64, 256 threads, 2 CTAs/SM, cp.async double-buffer.
// ---------------------------------------------------------------------------
#define A_STR   264
#define AH_OFF  0                 // GEMM1: fp16 m tile (33792 B); then G_hi
#define AL_OFF  33792             // G_lo (GEMM2 only)
#define B0_OFF  67584             // stage s at B0 + s*16896
#define BG_OFF  101376
#define OV_OFF  102400
#define BO_OFF  103424
#define SMEM_BYTES 104448

// fp16 B chunk prefetch: [16][256] fp16, 8448 B into stage front
__device__ __forceinline__ void out_prefetch16(unsigned sbase, int stage,
        const __half* __restrict__ W16, int kk, int t) {
    unsigned bh = sbase + B0_OFF + stage * 16896;
    #pragma unroll
    for (int i = 0; i < 2; i++) {
        int f = t + i * 256;
        int row = f >> 5, c8 = (f & 31) << 3;
        cp16(bh + (row * A_STR + c8) * 2, W16 + (kk + row) * 256 + c8);
    }
}
// bf16 hi/lo chunk prefetch (GEMM2)
__device__ __forceinline__ void out_prefetch(unsigned sbase, int stage,
        const __nv_bfloat16* __restrict__ WHi,
        const __nv_bfloat16* __restrict__ WLo, int kk, int t) {
    unsigned bh = sbase + B0_OFF + stage * 16896;
    #pragma unroll
    for (int i = 0; i < 2; i++) {
        int f = t + i * 256;
        int row = f >> 5, c8 = (f & 31) << 3;
        unsigned off = (row * A_STR + c8) * 2;
        cp16(bh + off,        WHi + (kk + row) * 256 + c8);
        cp16(bh + 8448 + off, WLo + (kk + row) * 256 + c8);
    }
}

__global__ void __launch_bounds__(256, 2)
out_kernel(const float* __restrict__ m,
           const float* __restrict__ bg,
           const float* __restrict__ bo,
           float* __restrict__ out) {
    extern __shared__ char smc[];
    unsigned sbase = (unsigned)__cvta_generic_to_shared(smc);
    float* sBG = reinterpret_cast<float*>(smc + BG_OFF);
    float* sOV = reinterpret_cast<float*>(smc + OV_OFF);
    float* sBO = reinterpret_cast<float*>(smc + BO_OFF);

    int t = threadIdx.x;
    int lane = t & 31, wid = t >> 5;
    int wm = wid >> 1, wn = wid & 1;
    int n = blockIdx.y;
    long tok0 = (long)n * SLEN + (long)blockIdx.x * 64;

    sBG[t] = bg[t];
    sOV[t] = g_o_buf[n * HC + t];
    sBO[t] = bo[t];

    // load m tile [64][256] fp32 once -> fp16 smem (GEMM1 operand)
    #pragma unroll
    for (int i = 0; i < 16; i++) {
        int idx = t + i * 256;
        int row = idx >> 6;
        int c4  = (idx & 63) << 2;
        float4 v = *reinterpret_cast<const float4*>(m + (tok0 + row) * CIN + c4);
        char* p = smc + AH_OFF + (row * A_STR + c4) * 2;
        reinterpret_cast<__half2*>(p)[0] = __floats2half2_rn(v.x, v.y);
        reinterpret_cast<__half2*>(p)[1] = __floats2half2_rn(v.z, v.w);
    }
    __syncthreads();

    float acc[16][4];
    #pragma unroll
    for (int i = 0; i < 16; i++)
        #pragma unroll
        for (int j = 0; j < 4; j++) acc[i][j] = 0.f;

    // ---- GEMM1: x = M @ Wg, fp16 single-MMA ----
    out_prefetch16(sbase, 0, g_Wg16, 0, t);
    CP_COMMIT();
    for (int c = 0; c < 16; c++) {
        CP_WAIT0();
        __syncthreads();
        if (c < 15) { out_prefetch16(sbase, (c + 1) & 1, g_Wg16, (c + 1) * 16, t); CP_COMMIT(); }
        else        { out_prefetch(sbase, 0, g_WoHi, g_WoLo, 0, t); CP_COMMIT(); }
        int kk = c * 16;
        unsigned bhb = sbase + B0_OFF + (c & 1) * 16896;

        unsigned a16[4];
        unsigned aaddr = sbase + AH_OFF +
            ((wm * 16 + (lane & 15)) * A_STR + kk + ((lane >> 4) << 3)) * 2;
        ldsm4(a16, aaddr);

        #pragma unroll
        for (int nb = 0; nb < 8; nb++) {
            int n0 = wn * 128 + nb * 16;
            unsigned baddr = bhb +
                ((lane & 15) * A_STR + n0 + ((lane >> 4) << 3)) * 2;
            unsigned bh4[4];
            ldsm4t(bh4, baddr);
            mma_fp16(acc[nb * 2],     a16, bh4[0], bh4[1]);
            mma_fp16(acc[nb * 2 + 1], a16, bh4[2], bh4[3]);
        }
    }
    __syncthreads();   // done reading fp16 A; epilogue rewrites A region

    // ---- epilogue 1: G = ov * sigmoid(acc + bg), split into Ah/Al (bf16) ----
    #pragma unroll
    for (int nt = 0; nt < 16; nt++) {
        int col0 = wn * 128 + nt * 8 + (lane & 3) * 2;
        int r0   = wm * 16 + (lane >> 2);
        float bg0 = sBG[col0], bg1 = sBG[col0 + 1];
        float ov0 = sOV[col0], ov1 = sOV[col0 + 1];
        float g0 = ov0 / (1.f + __expf(-(acc[nt][0] + bg0)));
        float g1 = ov1 / (1.f + __expf(-(acc[nt][1] + bg1)));
        float g2 = ov0 / (1.f + __expf(-(acc[nt][2] + bg0)));
        float g3 = ov1 / (1.f + __expf(-(acc[nt][3] + bg1)));
        __nv_bfloat162 h01 = __floats2bfloat162_rn(g0, g1);
        __nv_bfloat162 l01 = __floats2bfloat162_rn(g0 - __low2float(h01),
                                                   g1 - __high2float(h01));
        __nv_bfloat162 h23 = __floats2bfloat162_rn(g2, g3);
        __nv_bfloat162 l23 = __floats2bfloat162_rn(g2 - __low2float(h23),
                                                   g3 - __high2float(h23));
        *reinterpret_cast<__nv_bfloat162*>(smc + AH_OFF + (r0 * A_STR + col0) * 2)       = h01;
        *reinterpret_cast<__nv_bfloat162*>(smc + AL_OFF + (r0 * A_STR + col0) * 2)       = l01;
        *reinterpret_cast<__nv_bfloat162*>(smc + AH_OFF + ((r0 + 8) * A_STR + col0) * 2) = h23;
        *reinterpret_cast<__nv_bfloat162*>(smc + AL_OFF + ((r0 + 8) * A_STR + col0) * 2) = l23;
        acc[nt][0] = acc[nt][1] = acc[nt][2] = acc[nt][3] = 0.f;
    }
    __syncthreads();

    // ---- GEMM2: G @ Wo, bf16x3 (chunk 0 already in flight) ----
    for (int c = 0; c < 16; c++) {
        CP_WAIT0();
        __syncthreads();
        if (c < 15) { out_prefetch(sbase, (c + 1) & 1, g_WoHi, g_WoLo, (c + 1) * 16, t); CP_COMMIT(); }
        int kk = c * 16;
        unsigned bhb = sbase + B0_OFF + (c & 1) * 16896;

        unsigned ah[4], al[4];
        unsigned aaddr = sbase + AH_OFF +
            ((wm * 16 + (lane & 15)) * A_STR + kk + ((lane >> 4) << 3)) * 2;
        ldsm4(ah, aaddr);
        ldsm4(al, aaddr + AL_OFF);

        #pragma unroll
        for (int nb = 0; nb < 8; nb++) {
            int n0 = wn * 128 + nb * 16;
            unsigned baddr = bhb +
                ((lane & 15) * A_STR + n0 + ((lane >> 4) << 3)) * 2;
            unsigned bh4[4], bl4[4];
            ldsm4t(bh4, baddr);
            ldsm4t(bl4, baddr + 8448);
            mma_bf16(acc[nb * 2],     ah, bh4[0], bh4[1]);
            mma_bf16(acc[nb * 2],     ah, bl4[0], bl4[1]);
            mma_bf16(acc[nb * 2],     al, bh4[0], bh4[1]);
            mma_bf16(acc[nb * 2 + 1], ah, bh4[2], bh4[3]);
            mma_bf16(acc[nb * 2 + 1], ah, bl4[2], bl4[3]);
            mma_bf16(acc[nb * 2 + 1], al, bh4[2], bh4[3]);
        }
    }

    // ---- epilogue 2: + bo, write out ----
    #pragma unroll
    for (int nt = 0; nt < 16; nt++) {
        int col0 = wn * 128 + nt * 8 + (lane & 3) * 2;
        int r0   = wm * 16 + (lane >> 2);
        float2 o0 = make_float2(acc[nt][0] + sBO[col0], acc[nt][1] + sBO[col0 + 1]);
        float2 o1 = make_float2(acc[nt][2] + sBO[col0], acc[nt][3] + sBO[col0 + 1]);
        *reinterpret_cast<float2*>(out + (tok0 + r0) * CIN + col0)     = o0;
        *reinterpret_cast<float2*>(out + (tok0 + r0 + 8) * CIN + col0) = o1;
    }
}

// ---------------------------------------------------------------------------
extern "C" void kernel_launch(void* const* d_in, const int* in_sizes, int n_in,
                              void* d_out, int out_size) {
    const float* m    = (const float*)d_in[0];
    const float* mask = (const float*)d_in[1];
    const float* Wq   = (const float*)d_in[2];
    const float* Wk   = (const float*)d_in[3];
    const float* Wv   = (const float*)d_in[4];
    const float* Wg   = (const float*)d_in[5];
    const float* bg   = (const float*)d_in[6];
    const float* Wo   = (const float*)d_in[7];
    const float* bo   = (const float*)d_in[8];
    float* out = (float*)d_out;

    wconv_kernel<<<64, 256>>>(Wg, Wo, Wk, Wv);

    cudaFuncSetAttribute(kv_kernel,
                         cudaFuncAttributeMaxDynamicSharedMemorySize, KV_SMEM);
    kv_kernel<<<(NROWS * SLEN) / 64, 256, KV_SMEM>>>(m, mask);

    q2_kernel<<<NROWS, 256>>>(Wq);

    attn_part_kernel<<<dim3(NROWS, 4), 256>>>(mask);
    attn_merge_kernel<<<NROWS, 256>>>();

    cudaFuncSetAttribute(out_kernel,
                         cudaFuncAttributeMaxDynamicSharedMemorySize, SMEM_BYTES);
    out_kernel<<<dim3(SLEN / 64, NROWS), 256, SMEM_BYTES>>>(m, bg, bo, out);
}

// round 13
// speedup vs baseline: 1.9565x; 1.4999x over previous
#include <cuda_runtime.h>
#include <cuda_bf16.h>
#include <cuda_fp16.h>
#include <math.h>

#define NROWS 384
#define SLEN  1024
#define CIN   256
#define CH    32
#define NH    8
#define HC    256   // NH*CH

// Scratch (no cudaMalloc allowed).
__device__ float g_q_buf[NROWS * HC];
__device__ float g_o_buf[NROWS * HC];
__device__ float g_k_buf[(size_t)NROWS * SLEN * CH];
__device__ float g_v_buf[(size_t)NROWS * SLEN * CH];
// Weights: Wg, Wo in fp16 (single-MMA paths, error budget verified R12);
// Wk|Wv in bf16 hi/lo (softmax path keeps full precision).
__device__ __half        g_Wg16[CIN * HC];
__device__ __half        g_Wo16[HC * CIN];
__device__ __nv_bfloat16 g_WkvHi[CIN * 64], g_WkvLo[CIN * 64];
// Masked-mean partials: [tile 0..15][n][c] and [tile][n]
__device__ float g_qpart[16 * NROWS * CIN];
__device__ float g_mpart[16 * NROWS];
// Split-S attention partials: [quarter][n][hc] and stats [quarter][n][h][2]
__device__ float g_opart[4 * NROWS * HC];
__device__ float g_stat[4 * NROWS * NH * 2];

// ---------------------------------------------------------------------------
// cp.async helpers
// ---------------------------------------------------------------------------
__device__ __forceinline__ void cp16(unsigned saddr, const void* g) {
    asm volatile("cp.async.cg.shared.global [%0], [%1], 16;" :: "r"(saddr), "l"(g));
}
#define CP_COMMIT() asm volatile("cp.async.commit_group;" ::: "memory")
#define CP_WAIT0()  asm volatile("cp.async.wait_group 0;" ::: "memory")

// ---------------------------------------------------------------------------
// Kernel 0: weight conversion (Wg,Wo->fp16; Wk|Wv->bf16 hi/lo)
// ---------------------------------------------------------------------------
__global__ void wconv_kernel(const float* __restrict__ Wg,
                             const float* __restrict__ Wo,
                             const float* __restrict__ Wk,
                             const float* __restrict__ Wv) {
    int i = (blockIdx.x * 256 + threadIdx.x) * 4;  // 65536 elems per big matrix
    {
        float4 v = *reinterpret_cast<const float4*>(Wg + i);
        *reinterpret_cast<__half2*>(g_Wg16 + i)     = __floats2half2_rn(v.x, v.y);
        *reinterpret_cast<__half2*>(g_Wg16 + i + 2) = __floats2half2_rn(v.z, v.w);
    }
    {
        float4 v = *reinterpret_cast<const float4*>(Wo + i);
        *reinterpret_cast<__half2*>(g_Wo16 + i)     = __floats2half2_rn(v.x, v.y);
        *reinterpret_cast<__half2*>(g_Wo16 + i + 2) = __floats2half2_rn(v.z, v.w);
    }
    if (i < CIN * 64) {  // combined Wk|Wv: row k, col j (j<32 => Wk, else Wv)
        int k = i >> 6, j = i & 63;
        float4 v = (j < 32)
            ? *reinterpret_cast<const float4*>(Wk + k * CH + j)
            : *reinterpret_cast<const float4*>(Wv + k * CH + (j - 32));
        __nv_bfloat162 h01 = __floats2bfloat162_rn(v.x, v.y);
        __nv_bfloat162 h23 = __floats2bfloat162_rn(v.z, v.w);
        __nv_bfloat162 l01 = __floats2bfloat162_rn(v.x - __low2float(h01),
                                                   v.y - __high2float(h01));
        __nv_bfloat162 l23 = __floats2bfloat162_rn(v.z - __low2float(h23),
                                                   v.w - __high2float(h23));
        *reinterpret_cast<__nv_bfloat162*>(g_WkvHi + i)     = h01;
        *reinterpret_cast<__nv_bfloat162*>(g_WkvHi + i + 2) = h23;
        *reinterpret_cast<__nv_bfloat162*>(g_WkvLo + i)     = l01;
        *reinterpret_cast<__nv_bfloat162*>(g_WkvLo + i + 2) = l23;
    }
}

// ---------------------------------------------------------------------------
// mma helpers
// ---------------------------------------------------------------------------
__device__ __forceinline__ void ldsm4(unsigned r[4], unsigned addr) {
    asm volatile("ldmatrix.sync.aligned.m8n8.x4.shared.b16 {%0,%1,%2,%3}, [%4];"
        : "=r"(r[0]), "=r"(r[1]), "=r"(r[2]), "=r"(r[3]) : "r"(addr));
}
__device__ __forceinline__ void ldsm4t(unsigned r[4], unsigned addr) {
    asm volatile("ldmatrix.sync.aligned.m8n8.x4.trans.shared.b16 {%0,%1,%2,%3}, [%4];"
        : "=r"(r[0]), "=r"(r[1]), "=r"(r[2]), "=r"(r[3]) : "r"(addr));
}
__device__ __forceinline__ void mma_bf16(float c[4], const unsigned a[4],
                                         unsigned b0, unsigned b1) {
    asm volatile("mma.sync.aligned.m16n8k16.row.col.f32.bf16.bf16.f32 "
        "{%0,%1,%2,%3}, {%4,%5,%6,%7}, {%8,%9}, {%0,%1,%2,%3};"
        : "+f"(c[0]), "+f"(c[1]), "+f"(c[2]), "+f"(c[3])
        : "r"(a[0]), "r"(a[1]), "r"(a[2]), "r"(a[3]), "r"(b0), "r"(b1));
}
__device__ __forceinline__ void mma_fp16(float c[4], const unsigned a[4],
                                         unsigned b0, unsigned b1) {
    asm volatile("mma.sync.aligned.m16n8k16.row.col.f32.f16.f16.f32 "
        "{%0,%1,%2,%3}, {%4,%5,%6,%7}, {%8,%9}, {%0,%1,%2,%3};"
        : "+f"(c[0]), "+f"(c[1]), "+f"(c[2]), "+f"(c[3])
        : "r"(a[0]), "r"(a[1]), "r"(a[2]), "r"(a[3]), "r"(b0), "r"(b1));
}
__device__ __forceinline__ void split_store(char* ph, char* pl, float4 v) {
    __nv_bfloat162 h01 = __floats2bfloat162_rn(v.x, v.y);
    __nv_bfloat162 h23 = __floats2bfloat162_rn(v.z, v.w);
    __nv_bfloat162 l01 = __floats2bfloat162_rn(v.x - __low2float(h01),
                                               v.y - __high2float(h01));
    __nv_bfloat162 l23 = __floats2bfloat162_rn(v.z - __low2float(h23),
                                               v.w - __high2float(h23));
    reinterpret_cast<__nv_bfloat162*>(ph)[0] = h01;
    reinterpret_cast<__nv_bfloat162*>(ph)[1] = h23;
    reinterpret_cast<__nv_bfloat162*>(pl)[0] = l01;
    reinterpret_cast<__nv_bfloat162*>(pl)[1] = l23;
}

// ---------------------------------------------------------------------------
// Kernel 2: k|v = m @ (Wk|Wv), bf16x3 + fused masked-mean partials (kept)
// ---------------------------------------------------------------------------
#define KA_STR  264
#define KAH_OFF 0
#define KAL_OFF 33792
#define KB_STR  72
#define KB0_OFF 67584
#define KV_SMEM 76800

__device__ __forceinline__ void kv_prefetch(unsigned sbase, int stage, int kk, int t) {
    int f = t & 127;
    int row = f >> 3, c8 = (f & 7) << 3;
    unsigned dst = sbase + KB0_OFF + stage * 4608 + ((t < 128) ? 0 : 2304)
                 + (row * KB_STR + c8) * 2;
    const __nv_bfloat16* src = ((t < 128) ? g_WkvHi : g_WkvLo) + (kk + row) * 64 + c8;
    cp16(dst, src);
}

__global__ void __launch_bounds__(256, 2)
kv_kernel(const float* __restrict__ m, const float* __restrict__ mask) {
    extern __shared__ char smc[];
    __shared__ float mask_sm[64];
    unsigned sbase = (unsigned)__cvta_generic_to_shared(smc);
    int t = threadIdx.x;
    int lane = t & 31, wid = t >> 5;
    int wm = wid >> 1, wn = wid & 1;
    int n    = blockIdx.x >> 4;
    int tile = blockIdx.x & 15;
    long r0g = (long)blockIdx.x * 64;

    if (t < 64) mask_sm[t] = mask[(size_t)n * SLEN + tile * 64 + t];

    #pragma unroll
    for (int i = 0; i < 16; i++) {
        int idx = t + i * 256;
        int row = idx >> 6;
        int c4  = (idx & 63) << 2;
        float4 v = *reinterpret_cast<const float4*>(m + (r0g + row) * CIN + c4);
        split_store(smc + KAH_OFF + (row * KA_STR + c4) * 2,
                    smc + KAL_OFF + (row * KA_STR + c4) * 2, v);
    }
    __syncthreads();

    kv_prefetch(sbase, 0, 0, t);
    CP_COMMIT();

    {
        float qs = 0.f;
        #pragma unroll 8
        for (int r = 0; r < 64; r++) {
            float hi = __bfloat162float(*reinterpret_cast<__nv_bfloat16*>(
                smc + KAH_OFF + (r * KA_STR + t) * 2));
            float lo = __bfloat162float(*reinterpret_cast<__nv_bfloat16*>(
                smc + KAL_OFF + (r * KA_STR + t) * 2));
            qs = fmaf(hi + lo, mask_sm[r], qs);
        }
        g_qpart[(tile * NROWS + n) * CIN + t] = qs;
        if (t == 0) {
            float ms = 0.f;
            for (int r = 0; r < 64; r++) ms += mask_sm[r];
            g_mpart[tile * NROWS + n] = ms;
        }
    }

    float acc[4][4];
    #pragma unroll
    for (int i = 0; i < 4; i++)
        #pragma unroll
        for (int j = 0; j < 4; j++) acc[i][j] = 0.f;

    for (int c = 0; c < 16; c++) {
        CP_WAIT0();
        __syncthreads();
        if (c < 15) { kv_prefetch(sbase, (c + 1) & 1, (c + 1) * 16, t); CP_COMMIT(); }
        int kk = c * 16;
        unsigned kbh = sbase + KB0_OFF + (c & 1) * 4608;

        unsigned ah[4], al[4];
        unsigned aaddr = sbase + KAH_OFF +
            ((wm * 16 + (lane & 15)) * KA_STR + kk + ((lane >> 4) << 3)) * 2;
        ldsm4(ah, aaddr);
        ldsm4(al, aaddr + KAL_OFF);

        #pragma unroll
        for (int nb = 0; nb < 2; nb++) {
            int col0 = wn * 32 + nb * 16;
            unsigned baddr = kbh +
                ((lane & 15) * KB_STR + col0 + ((lane >> 4) << 3)) * 2;
            unsigned bh[4], bl[4];
            ldsm4t(bh, baddr);
            ldsm4t(bl, baddr + 2304);
            mma_bf16(acc[nb * 2],     ah, bh[0], bh[1]);
            mma_bf16(acc[nb * 2],     ah, bl[0], bl[1]);
            mma_bf16(acc[nb * 2],     al, bh[0], bh[1]);
            mma_bf16(acc[nb * 2 + 1], ah, bh[2], bh[3]);
            mma_bf16(acc[nb * 2 + 1], ah, bl[2], bl[3]);
            mma_bf16(acc[nb * 2 + 1], al, bh[2], bh[3]);
        }
    }

    #pragma unroll
    for (int nb = 0; nb < 2; nb++) {
        #pragma unroll
        for (int half = 0; half < 2; half++) {
            int col = wn * 32 + nb * 16 + half * 8 + (lane & 3) * 2;
            int r0  = wm * 16 + (lane >> 2);
            float* f = acc[nb * 2 + half];
            float* dst = (col < CH) ? (g_k_buf + ((r0g + r0) * CH + col))
                                    : (g_v_buf + ((r0g + r0) * CH + col - CH));
            *reinterpret_cast<float2*>(dst) = make_float2(f[0], f[1]);
            dst += 8 * CH;
            *reinterpret_cast<float2*>(dst) = make_float2(f[2], f[3]);
        }
    }
}

// ---------------------------------------------------------------------------
// Kernel 2b: finish mean + q = (mean @ Wq) * C^-0.5
// ---------------------------------------------------------------------------
__global__ void q2_kernel(const float* __restrict__ Wq) {
    int n = blockIdx.x, t = threadIdx.x;
    __shared__ float qm[CIN];
    float s = 0.f;
    #pragma unroll
    for (int p = 0; p < 16; p++) s += g_qpart[(p * NROWS + n) * CIN + t];
    float mk = 0.f;
    #pragma unroll
    for (int p = 0; p < 16; p++) mk += g_mpart[p * NROWS + n];
    qm[t] = s / (mk + 1e-10f);
    __syncthreads();
    float acc = 0.f;
    #pragma unroll 8
    for (int c = 0; c < CIN; c++) acc = fmaf(qm[c], Wq[c * HC + t], acc);
    g_q_buf[n * HC + t] = acc * 0.17677669529663687f;
}

// ---------------------------------------------------------------------------
// Kernel 3a: split-S attention partials, 4 quarters. grid (384, 4).
// ---------------------------------------------------------------------------
#define S4 256

__global__ void __launch_bounds__(256)
attn_part_kernel(const float* __restrict__ mask) {
    int n = blockIdx.x, qt = blockIdx.y, t = threadIdx.x;
    int s0 = qt * S4;
    __shared__ float q_sm[HC];
    __shared__ float p_sm[NH * S4];   // 8 KB

    q_sm[t] = g_q_buf[n * HC + t];
    __syncthreads();

    const float* krow = g_k_buf + ((size_t)n * SLEN + s0) * CH;
    const float* vrow = g_v_buf + ((size_t)n * SLEN + s0) * CH;
    const float* mk   = mask + (size_t)n * SLEN + s0;

    {
        int s = t;
        float kreg[32];
        #pragma unroll
        for (int q = 0; q < 8; q++)
            *reinterpret_cast<float4*>(kreg + q * 4) =
                *reinterpret_cast<const float4*>(krow + (size_t)s * CH + q * 4);
        float bias = 1e9f * (mk[s] - 1.0f);
        #pragma unroll
        for (int h = 0; h < NH; h++) {
            float d = 0.f;
            #pragma unroll
            for (int j = 0; j < 32; j++) d = fmaf(q_sm[h * 32 + j], kreg[j], d);
            p_sm[h * S4 + s] = d + bias;
        }
    }
    __syncthreads();

    int h = t >> 5, lane = t & 31;
    float mx = -3.0e38f;
    for (int s = lane; s < S4; s += 32) mx = fmaxf(mx, p_sm[h * S4 + s]);
    #pragma unroll
    for (int off = 16; off > 0; off >>= 1)
        mx = fmaxf(mx, __shfl_xor_sync(0xffffffffu, mx, off));

    float sum = 0.f;
    for (int s = lane; s < S4; s += 32) {
        float e = __expf(p_sm[h * S4 + s] - mx);
        p_sm[h * S4 + s] = e;
        sum += e;
    }
    #pragma unroll
    for (int off = 16; off > 0; off >>= 1)
        sum += __shfl_xor_sync(0xffffffffu, sum, off);
    if (lane == 0) {
        g_stat[((qt * NROWS + n) * NH + h) * 2]     = mx;
        g_stat[((qt * NROWS + n) * NH + h) * 2 + 1] = sum;
    }
    __syncthreads();

    // unnormalized p@v partial
    {
        int sg  = lane >> 3;
        int c4  = (lane & 7) << 2;
        float4 acc4 = make_float4(0.f, 0.f, 0.f, 0.f);
        const float* ph = p_sm + h * S4;
        #pragma unroll 4
        for (int s = sg; s < S4; s += 4) {
            float p = ph[s];
            float4 v4 = *reinterpret_cast<const float4*>(vrow + (size_t)s * CH + c4);
            acc4.x = fmaf(p, v4.x, acc4.x);
            acc4.y = fmaf(p, v4.y, acc4.y);
            acc4.z = fmaf(p, v4.z, acc4.z);
            acc4.w = fmaf(p, v4.w, acc4.w);
        }
        #pragma unroll
        for (int off = 8; off <= 16; off <<= 1) {
            acc4.x += __shfl_xor_sync(0xffffffffu, acc4.x, off);
            acc4.y += __shfl_xor_sync(0xffffffffu, acc4.y, off);
            acc4.z += __shfl_xor_sync(0xffffffffu, acc4.z, off);
            acc4.w += __shfl_xor_sync(0xffffffffu, acc4.w, off);
        }
        if (sg == 0)
            *reinterpret_cast<float4*>(
                g_opart + (qt * NROWS + n) * HC + h * CH + c4) = acc4;
    }
}

// ---------------------------------------------------------------------------
// Kernel 3b: merge the four S-quarters
// ---------------------------------------------------------------------------
__global__ void attn_merge_kernel() {
    int n = blockIdx.x, t = threadIdx.x;
    int h = t >> 5;
    float mq[4], sq[4];
    #pragma unroll
    for (int p = 0; p < 4; p++) {
        mq[p] = g_stat[((p * NROWS + n) * NH + h) * 2];
        sq[p] = g_stat[((p * NROWS + n) * NH + h) * 2 + 1];
    }
    float M = fmaxf(fmaxf(mq[0], mq[1]), fmaxf(mq[2], mq[3]));
    float num = 0.f, den = 0.f;
    #pragma unroll
    for (int p = 0; p < 4; p++) {
        float w = __expf(mq[p] - M);
        num = fmaf(w, g_opart[(p * NROWS + n) * HC + t], num);
        den = fmaf(w, sq[p], den);
    }
    g_o_buf[n * HC + t] = num / den;
}

// ---------------------------------------------------------------------------
// Kernel 4: out_kernel.  BOTH GEMMs fp16 single-MMA (error budget: GEMM1
// sigmoid-damped, GEMM2 ~1-3e-4 by calibrated model; combined << 1e-3).
// BM=64, 256 threads, 2 CTAs/SM, cp.async double-buffer, ~54 KB smem.
// ---------------------------------------------------------------------------
#define A_STR   264
#define AH_OFF  0                 // fp16 m tile, then fp16 G tile (33792 B)
#define B0_OFF  33792             // stage s at B0 + s*8448 (fp16 [16][256])
#define BG_OFF  50688
#define OV_OFF  51712
#define BO_OFF  52736
#define SMEM_BYTES 53760

__device__ __forceinline__ void out_prefetch16(unsigned sbase, int stage,
        const __half* __restrict__ W16, int kk, int t) {
    unsigned bh = sbase + B0_OFF + stage * 8448;
    #pragma unroll
    for (int i = 0; i < 2; i++) {
        int f = t + i * 256;
        int row = f >> 5, c8 = (f & 31) << 3;
        cp16(bh + (row * A_STR + c8) * 2, W16 + (kk + row) * 256 + c8);
    }
}

// One 64x256x256 fp16 GEMM with double-buffered weight chunks.
// If pre0, chunk 0 already committed by caller.  At last chunk, prefetches
// Wnext chunk 0 (if non-null) so the following epilogue overlaps the load.
__device__ __forceinline__ void gemm_fp16x1(
    unsigned sbase, const __half* __restrict__ W16,
    float acc[16][4], int t, int lane, int wm, int wn, bool pre0,
    const __half* __restrict__ Wnext)
{
    if (!pre0) { out_prefetch16(sbase, 0, W16, 0, t); CP_COMMIT(); }
    for (int c = 0; c < 16; c++) {
        CP_WAIT0();
        __syncthreads();
        if (c < 15)    { out_prefetch16(sbase, (c + 1) & 1, W16, (c + 1) * 16, t); CP_COMMIT(); }
        else if (Wnext){ out_prefetch16(sbase, 0, Wnext, 0, t); CP_COMMIT(); }
        int kk = c * 16;
        unsigned bhb = sbase + B0_OFF + (c & 1) * 8448;

        unsigned a16[4];
        unsigned aaddr = sbase + AH_OFF +
            ((wm * 16 + (lane & 15)) * A_STR + kk + ((lane >> 4) << 3)) * 2;
        ldsm4(a16, aaddr);

        #pragma unroll
        for (int nb = 0; nb < 8; nb++) {
            int n0 = wn * 128 + nb * 16;
            unsigned baddr = bhb +
                ((lane & 15) * A_STR + n0 + ((lane >> 4) << 3)) * 2;
            unsigned bh4[4];
            ldsm4t(bh4, baddr);
            mma_fp16(acc[nb * 2],     a16, bh4[0], bh4[1]);
            mma_fp16(acc[nb * 2 + 1], a16, bh4[2], bh4[3]);
        }
    }
    __syncthreads();   // all warps done reading A before caller rewrites it
}

__global__ void __launch_bounds__(256, 2)
out_kernel(const float* __restrict__ m,
           const float* __restrict__ bg,
           const float* __restrict__ bo,
           float* __restrict__ out) {
    extern __shared__ char smc[];
    unsigned sbase = (unsigned)__cvta_generic_to_shared(smc);
    float* sBG = reinterpret_cast<float*>(smc + BG_OFF);
    float* sOV = reinterpret_cast<float*>(smc + OV_OFF);
    float* sBO = reinterpret_cast<float*>(smc + BO_OFF);

    int t = threadIdx.x;
    int lane = t & 31, wid = t >> 5;
    int wm = wid >> 1, wn = wid & 1;
    int n = blockIdx.y;
    long tok0 = (long)n * SLEN + (long)blockIdx.x * 64;

    sBG[t] = bg[t];
    sOV[t] = g_o_buf[n * HC + t];
    sBO[t] = bo[t];

    // load m tile [64][256] fp32 once -> fp16 smem (GEMM1 operand)
    #pragma unroll
    for (int i = 0; i < 16; i++) {
        int idx = t + i * 256;
        int row = idx >> 6;
        int c4  = (idx & 63) << 2;
        float4 v = *reinterpret_cast<const float4*>(m + (tok0 + row) * CIN + c4);
        char* p = smc + AH_OFF + (row * A_STR + c4) * 2;
        reinterpret_cast<__half2*>(p)[0] = __floats2half2_rn(v.x, v.y);
        reinterpret_cast<__half2*>(p)[1] = __floats2half2_rn(v.z, v.w);
    }
    __syncthreads();

    float acc[16][4];
    #pragma unroll
    for (int i = 0; i < 16; i++)
        #pragma unroll
        for (int j = 0; j < 4; j++) acc[i][j] = 0.f;

    // ---- GEMM1: x = M @ Wg (fp16; tail prefetches Wo chunk 0) ----
    gemm_fp16x1(sbase, g_Wg16, acc, t, lane, wm, wn, false, g_Wo16);

    // ---- epilogue 1: G = ov * sigmoid(acc + bg) -> fp16 A tile ----
    #pragma unroll
    for (int nt = 0; nt < 16; nt++) {
        int col0 = wn * 128 + nt * 8 + (lane & 3) * 2;
        int r0   = wm * 16 + (lane >> 2);
        float bg0 = sBG[col0], bg1 = sBG[col0 + 1];
        float ov0 = sOV[col0], ov1 = sOV[col0 + 1];
        float g0 = ov0 / (1.f + __expf(-(acc[nt][0] + bg0)));
        float g1 = ov1 / (1.f + __expf(-(acc[nt][1] + bg1)));
        float g2 = ov0 / (1.f + __expf(-(acc[nt][2] + bg0)));
        float g3 = ov1 / (1.f + __expf(-(acc[nt][3] + bg1)));
        *reinterpret_cast<__half2*>(smc + AH_OFF + (r0 * A_STR + col0) * 2)
            = __floats2half2_rn(g0, g1);
        *reinterpret_cast<__half2*>(smc + AH_OFF + ((r0 + 8) * A_STR + col0) * 2)
            = __floats2half2_rn(g2, g3);
        acc[nt][0] = acc[nt][1] = acc[nt][2] = acc[nt][3] = 0.f;
    }
    __syncthreads();

    // ---- GEMM2: out = G @ Wo (fp16; chunk 0 already in flight) ----
    gemm_fp16x1(sbase, g_Wo16, acc, t, lane, wm, wn, true, (const __half*)0);

    // ---- epilogue 2: + bo, write out ----
    #pragma unroll
    for (int nt = 0; nt < 16; nt++) {
        int col0 = wn * 128 + nt * 8 + (lane & 3) * 2;
        int r0   = wm * 16 + (lane >> 2);
        float2 o0 = make_float2(acc[nt][0] + sBO[col0], acc[nt][1] + sBO[col0 + 1]);
        float2 o1 = make_float2(acc[nt][2] + sBO[col0], acc[nt][3] + sBO[col0 + 1]);
        *reinterpret_cast<float2*>(out + (tok0 + r0) * CIN + col0)     = o0;
        *reinterpret_cast<float2*>(out + (tok0 + r0 + 8) * CIN + col0) = o1;
    }
}

// ---------------------------------------------------------------------------
extern "C" void kernel_launch(void* const* d_in, const int* in_sizes, int n_in,
                              void* d_out, int out_size) {
    const float* m    = (const float*)d_in[0];
    const float* mask = (const float*)d_in[1];
    const float* Wq   = (const float*)d_in[2];
    const float* Wk   = (const float*)d_in[3];
    const float* Wv   = (const float*)d_in[4];
    const float* Wg   = (const float*)d_in[5];
    const float* bg   = (const float*)d_in[6];
    const float* Wo   = (const float*)d_in[7];
    const float* bo   = (const float*)d_in[8];
    float* out = (float*)d_out;

    wconv_kernel<<<64, 256>>>(Wg, Wo, Wk, Wv);

    cudaFuncSetAttribute(kv_kernel,
                         cudaFuncAttributeMaxDynamicSharedMemorySize, KV_SMEM);
    kv_kernel<<<(NROWS * SLEN) / 64, 256, KV_SMEM>>>(m, mask);

    q2_kernel<<<NROWS, 256>>>(Wq);

    attn_part_kernel<<<dim3(NROWS, 4), 256>>>(mask);
    attn_merge_kernel<<<NROWS, 256>>>();

    cudaFuncSetAttribute(out_kernel,
                         cudaFuncAttributeMaxDynamicSharedMemorySize, SMEM_BYTES);
    out_kernel<<<dim3(SLEN / 64, NROWS), 256, SMEM_BYTES>>>(m, bg, bo, out);
}

// round 14
// speedup vs baseline: 2.1831x; 1.1158x over previous
#include <cuda_runtime.h>
#include <cuda_bf16.h>
#include <cuda_fp16.h>
#include <math.h>

#define NROWS 384
#define SLEN  1024
#define CIN   256
#define CH    32
#define NH    8
#define HC    256   // NH*CH

// Scratch (no cudaMalloc allowed).
__device__ float g_q_buf[NROWS * HC];
__device__ float g_o_buf[NROWS * HC];
__device__ float g_k_buf[(size_t)NROWS * SLEN * CH];
__device__ float g_v_buf[(size_t)NROWS * SLEN * CH];
// Weights, all fp16 single-MMA paths (error budget calibrated R12/R13):
__device__ __half g_Wg16[CIN * HC];
__device__ __half g_Wo16[HC * CIN];
__device__ __half g_Wkv16[CIN * 64];          // Wk|Wv combined, [K,64]
// Masked-mean partials: [tile 0..15][n][c] and [tile][n]
__device__ float g_qpart[16 * NROWS * CIN];
__device__ float g_mpart[16 * NROWS];
// Split-S attention partials: [quarter][n][hc] and stats [quarter][n][h][2]
__device__ float g_opart[4 * NROWS * HC];
__device__ float g_stat[4 * NROWS * NH * 2];

// ---------------------------------------------------------------------------
// cp.async helpers
// ---------------------------------------------------------------------------
__device__ __forceinline__ void cp16(unsigned saddr, const void* g) {
    asm volatile("cp.async.cg.shared.global [%0], [%1], 16;" :: "r"(saddr), "l"(g));
}
#define CP_COMMIT() asm volatile("cp.async.commit_group;" ::: "memory")
#define CP_WAIT0()  asm volatile("cp.async.wait_group 0;" ::: "memory")

// ---------------------------------------------------------------------------
// Kernel 0: weight conversion (all fp16)
// ---------------------------------------------------------------------------
__global__ void wconv_kernel(const float* __restrict__ Wg,
                             const float* __restrict__ Wo,
                             const float* __restrict__ Wk,
                             const float* __restrict__ Wv) {
    int i = (blockIdx.x * 256 + threadIdx.x) * 4;  // 65536 elems per big matrix
    {
        float4 v = *reinterpret_cast<const float4*>(Wg + i);
        *reinterpret_cast<__half2*>(g_Wg16 + i)     = __floats2half2_rn(v.x, v.y);
        *reinterpret_cast<__half2*>(g_Wg16 + i + 2) = __floats2half2_rn(v.z, v.w);
    }
    {
        float4 v = *reinterpret_cast<const float4*>(Wo + i);
        *reinterpret_cast<__half2*>(g_Wo16 + i)     = __floats2half2_rn(v.x, v.y);
        *reinterpret_cast<__half2*>(g_Wo16 + i + 2) = __floats2half2_rn(v.z, v.w);
    }
    if (i < CIN * 64) {  // combined Wk|Wv: row k, col j (j<32 => Wk, else Wv)
        int k = i >> 6, j = i & 63;
        float4 v = (j < 32)
            ? *reinterpret_cast<const float4*>(Wk + k * CH + j)
            : *reinterpret_cast<const float4*>(Wv + k * CH + (j - 32));
        *reinterpret_cast<__half2*>(g_Wkv16 + i)     = __floats2half2_rn(v.x, v.y);
        *reinterpret_cast<__half2*>(g_Wkv16 + i + 2) = __floats2half2_rn(v.z, v.w);
    }
}

// ---------------------------------------------------------------------------
// mma helpers
// ---------------------------------------------------------------------------
__device__ __forceinline__ void ldsm4(unsigned r[4], unsigned addr) {
    asm volatile("ldmatrix.sync.aligned.m8n8.x4.shared.b16 {%0,%1,%2,%3}, [%4];"
        : "=r"(r[0]), "=r"(r[1]), "=r"(r[2]), "=r"(r[3]) : "r"(addr));
}
__device__ __forceinline__ void ldsm4t(unsigned r[4], unsigned addr) {
    asm volatile("ldmatrix.sync.aligned.m8n8.x4.trans.shared.b16 {%0,%1,%2,%3}, [%4];"
        : "=r"(r[0]), "=r"(r[1]), "=r"(r[2]), "=r"(r[3]) : "r"(addr));
}
__device__ __forceinline__ void mma_fp16(float c[4], const unsigned a[4],
                                         unsigned b0, unsigned b1) {
    asm volatile("mma.sync.aligned.m16n8k16.row.col.f32.f16.f16.f32 "
        "{%0,%1,%2,%3}, {%4,%5,%6,%7}, {%8,%9}, {%0,%1,%2,%3};"
        : "+f"(c[0]), "+f"(c[1]), "+f"(c[2]), "+f"(c[3])
        : "r"(a[0]), "r"(a[1]), "r"(a[2]), "r"(a[3]), "r"(b0), "r"(b1));
}

// ---------------------------------------------------------------------------
// Kernel 2: k|v = m @ (Wk|Wv), fp16 single-MMA + fused masked-mean partials.
// BM=64, 256 threads (8 warps in 4x2: 16 rows x 32 cols), ~38 KB smem.
// ---------------------------------------------------------------------------
#define KA_STR  264
#define KB_STR  72
#define KB0_OFF 33792             // stage s at KB0 + s*2304 (fp16 [16][64])
#define KV_SMEM 38400

__device__ __forceinline__ void kv_prefetch(unsigned sbase, int stage, int kk, int t) {
    if (t < 128) {
        int row = t >> 3, c8 = (t & 7) << 3;
        cp16(sbase + KB0_OFF + stage * 2304 + (row * KB_STR + c8) * 2,
             g_Wkv16 + (kk + row) * 64 + c8);
    }
}

__global__ void __launch_bounds__(256, 3)
kv_kernel(const float* __restrict__ m, const float* __restrict__ mask) {
    extern __shared__ char smc[];
    __shared__ float mask_sm[64];
    unsigned sbase = (unsigned)__cvta_generic_to_shared(smc);
    int t = threadIdx.x;
    int lane = t & 31, wid = t >> 5;
    int wm = wid >> 1, wn = wid & 1;
    int n    = blockIdx.x >> 4;
    int tile = blockIdx.x & 15;
    long r0g = (long)blockIdx.x * 64;

    if (t < 64) mask_sm[t] = mask[(size_t)n * SLEN + tile * 64 + t];

    // load m tile [64][256] fp32 -> fp16 smem
    #pragma unroll
    for (int i = 0; i < 16; i++) {
        int idx = t + i * 256;
        int row = idx >> 6;
        int c4  = (idx & 63) << 2;
        float4 v = *reinterpret_cast<const float4*>(m + (r0g + row) * CIN + c4);
        char* p = smc + (row * KA_STR + c4) * 2;
        reinterpret_cast<__half2*>(p)[0] = __floats2half2_rn(v.x, v.y);
        reinterpret_cast<__half2*>(p)[1] = __floats2half2_rn(v.z, v.w);
    }
    __syncthreads();

    kv_prefetch(sbase, 0, 0, t);
    CP_COMMIT();

    // masked-mean partial for channel t over this CTA's 64 tokens (fp16 m ok:
    // mean error ~1e-4 -> logit error ~2e-5 absolute, negligible)
    {
        float qs = 0.f;
        #pragma unroll 8
        for (int r = 0; r < 64; r++) {
            float mv = __half2float(*reinterpret_cast<__half*>(
                smc + (r * KA_STR + t) * 2));
            qs = fmaf(mv, mask_sm[r], qs);
        }
        g_qpart[(tile * NROWS + n) * CIN + t] = qs;
        if (t == 0) {
            float ms = 0.f;
            for (int r = 0; r < 64; r++) ms += mask_sm[r];
            g_mpart[tile * NROWS + n] = ms;
        }
    }

    float acc[4][4];
    #pragma unroll
    for (int i = 0; i < 4; i++)
        #pragma unroll
        for (int j = 0; j < 4; j++) acc[i][j] = 0.f;

    for (int c = 0; c < 16; c++) {
        CP_WAIT0();
        __syncthreads();
        if (c < 15) { kv_prefetch(sbase, (c + 1) & 1, (c + 1) * 16, t); CP_COMMIT(); }
        int kk = c * 16;
        unsigned kbh = sbase + KB0_OFF + (c & 1) * 2304;

        unsigned a16[4];
        unsigned aaddr = sbase +
            ((wm * 16 + (lane & 15)) * KA_STR + kk + ((lane >> 4) << 3)) * 2;
        ldsm4(a16, aaddr);

        #pragma unroll
        for (int nb = 0; nb < 2; nb++) {
            int col0 = wn * 32 + nb * 16;
            unsigned baddr = kbh +
                ((lane & 15) * KB_STR + col0 + ((lane >> 4) << 3)) * 2;
            unsigned bh[4];
            ldsm4t(bh, baddr);
            mma_fp16(acc[nb * 2],     a16, bh[0], bh[1]);
            mma_fp16(acc[nb * 2 + 1], a16, bh[2], bh[3]);
        }
    }

    // write k (cols 0..31) and v (cols 32..63)
    #pragma unroll
    for (int nb = 0; nb < 2; nb++) {
        #pragma unroll
        for (int half = 0; half < 2; half++) {
            int col = wn * 32 + nb * 16 + half * 8 + (lane & 3) * 2;
            int r0  = wm * 16 + (lane >> 2);
            float* f = acc[nb * 2 + half];
            float* dst = (col < CH) ? (g_k_buf + ((r0g + r0) * CH + col))
                                    : (g_v_buf + ((r0g + r0) * CH + col - CH));
            *reinterpret_cast<float2*>(dst) = make_float2(f[0], f[1]);
            dst += 8 * CH;
            *reinterpret_cast<float2*>(dst) = make_float2(f[2], f[3]);
        }
    }
}

// ---------------------------------------------------------------------------
// Kernel 2b: finish mean + q = (mean @ Wq) * C^-0.5
// ---------------------------------------------------------------------------
__global__ void q2_kernel(const float* __restrict__ Wq) {
    int n = blockIdx.x, t = threadIdx.x;
    __shared__ float qm[CIN];
    float s = 0.f;
    #pragma unroll
    for (int p = 0; p < 16; p++) s += g_qpart[(p * NROWS + n) * CIN + t];
    float mk = 0.f;
    #pragma unroll
    for (int p = 0; p < 16; p++) mk += g_mpart[p * NROWS + n];
    qm[t] = s / (mk + 1e-10f);
    __syncthreads();
    float acc = 0.f;
    #pragma unroll 8
    for (int c = 0; c < CIN; c++) acc = fmaf(qm[c], Wq[c * HC + t], acc);
    g_q_buf[n * HC + t] = acc * 0.17677669529663687f;
}

// ---------------------------------------------------------------------------
// Kernel 3a: split-S attention partials, 4 quarters. grid (384, 4).
// ---------------------------------------------------------------------------
#define S4 256

__global__ void __launch_bounds__(256)
attn_part_kernel(const float* __restrict__ mask) {
    int n = blockIdx.x, qt = blockIdx.y, t = threadIdx.x;
    int s0 = qt * S4;
    __shared__ float q_sm[HC];
    __shared__ float p_sm[NH * S4];   // 8 KB

    q_sm[t] = g_q_buf[n * HC + t];
    __syncthreads();

    const float* krow = g_k_buf + ((size_t)n * SLEN + s0) * CH;
    const float* vrow = g_v_buf + ((size_t)n * SLEN + s0) * CH;
    const float* mk   = mask + (size_t)n * SLEN + s0;

    {
        int s = t;
        float kreg[32];
        #pragma unroll
        for (int q = 0; q < 8; q++)
            *reinterpret_cast<float4*>(kreg + q * 4) =
                *reinterpret_cast<const float4*>(krow + (size_t)s * CH + q * 4);
        float bias = 1e9f * (mk[s] - 1.0f);
        #pragma unroll
        for (int h = 0; h < NH; h++) {
            float d = 0.f;
            #pragma unroll
            for (int j = 0; j < 32; j++) d = fmaf(q_sm[h * 32 + j], kreg[j], d);
            p_sm[h * S4 + s] = d + bias;
        }
    }
    __syncthreads();

    int h = t >> 5, lane = t & 31;
    float mx = -3.0e38f;
    for (int s = lane; s < S4; s += 32) mx = fmaxf(mx, p_sm[h * S4 + s]);
    #pragma unroll
    for (int off = 16; off > 0; off >>= 1)
        mx = fmaxf(mx, __shfl_xor_sync(0xffffffffu, mx, off));

    float sum = 0.f;
    for (int s = lane; s < S4; s += 32) {
        float e = __expf(p_sm[h * S4 + s] - mx);
        p_sm[h * S4 + s] = e;
        sum += e;
    }
    #pragma unroll
    for (int off = 16; off > 0; off >>= 1)
        sum += __shfl_xor_sync(0xffffffffu, sum, off);
    if (lane == 0) {
        g_stat[((qt * NROWS + n) * NH + h) * 2]     = mx;
        g_stat[((qt * NROWS + n) * NH + h) * 2 + 1] = sum;
    }
    __syncthreads();

    // unnormalized p@v partial
    {
        int sg  = lane >> 3;
        int c4  = (lane & 7) << 2;
        float4 acc4 = make_float4(0.f, 0.f, 0.f, 0.f);
        const float* ph = p_sm + h * S4;
        #pragma unroll 4
        for (int s = sg; s < S4; s += 4) {
            float p = ph[s];
            float4 v4 = *reinterpret_cast<const float4*>(vrow + (size_t)s * CH + c4);
            acc4.x = fmaf(p, v4.x, acc4.x);
            acc4.y = fmaf(p, v4.y, acc4.y);
            acc4.z = fmaf(p, v4.z, acc4.z);
            acc4.w = fmaf(p, v4.w, acc4.w);
        }
        #pragma unroll
        for (int off = 8; off <= 16; off <<= 1) {
            acc4.x += __shfl_xor_sync(0xffffffffu, acc4.x, off);
            acc4.y += __shfl_xor_sync(0xffffffffu, acc4.y, off);
            acc4.z += __shfl_xor_sync(0xffffffffu, acc4.z, off);
            acc4.w += __shfl_xor_sync(0xffffffffu, acc4.w, off);
        }
        if (sg == 0)
            *reinterpret_cast<float4*>(
                g_opart + (qt * NROWS + n) * HC + h * CH + c4) = acc4;
    }
}

// ---------------------------------------------------------------------------
// Kernel 3b: merge the four S-quarters
// ---------------------------------------------------------------------------
__global__ void attn_merge_kernel() {
    int n = blockIdx.x, t = threadIdx.x;
    int h = t >> 5;
    float mq[4], sq[4];
    #pragma unroll
    for (int p = 0; p < 4; p++) {
        mq[p] = g_stat[((p * NROWS + n) * NH + h) * 2];
        sq[p] = g_stat[((p * NROWS + n) * NH + h) * 2 + 1];
    }
    float M = fmaxf(fmaxf(mq[0], mq[1]), fmaxf(mq[2], mq[3]));
    float num = 0.f, den = 0.f;
    #pragma unroll
    for (int p = 0; p < 4; p++) {
        float w = __expf(mq[p] - M);
        num = fmaf(w, g_opart[(p * NROWS + n) * HC + t], num);
        den = fmaf(w, sq[p], den);
    }
    g_o_buf[n * HC + t] = num / den;
}

// ---------------------------------------------------------------------------
// Kernel 4: out_kernel, both GEMMs fp16 single-MMA, BK=32 (16 sync rounds
// total per GEMM -> 8).  BM=64, 256 threads, 2 CTAs/SM, ~71 KB smem.
// ---------------------------------------------------------------------------
#define A_STR   264
#define AH_OFF  0                 // fp16 m tile, then fp16 G tile (33792 B)
#define B0_OFF  33792             // stage s at B0 + s*16896 (fp16 [32][256])
#define BG_OFF  67584
#define OV_OFF  68608
#define BO_OFF  69632
#define SMEM_BYTES 70656

__device__ __forceinline__ void out_prefetch32(unsigned sbase, int stage,
        const __half* __restrict__ W16, int kk, int t) {
    unsigned bh = sbase + B0_OFF + stage * 16896;
    #pragma unroll
    for (int i = 0; i < 4; i++) {
        int f = t + i * 256;          // 0..1023
        int row = f >> 5, c8 = (f & 31) << 3;
        cp16(bh + (row * A_STR + c8) * 2, W16 + (kk + row) * 256 + c8);
    }
}

// One 64x256x256 fp16 GEMM, BK=32 double-buffered.
__device__ __forceinline__ void gemm_fp16x1(
    unsigned sbase, const __half* __restrict__ W16,
    float acc[16][4], int t, int lane, int wm, int wn, bool pre0,
    const __half* __restrict__ Wnext)
{
    if (!pre0) { out_prefetch32(sbase, 0, W16, 0, t); CP_COMMIT(); }
    for (int c = 0; c < 8; c++) {
        CP_WAIT0();
        __syncthreads();
        if (c < 7)     { out_prefetch32(sbase, (c + 1) & 1, W16, (c + 1) * 32, t); CP_COMMIT(); }
        else if (Wnext){ out_prefetch32(sbase, 0, Wnext, 0, t); CP_COMMIT(); }
        unsigned bhb = sbase + B0_OFF + (c & 1) * 16896;

        #pragma unroll
        for (int hkk = 0; hkk < 2; hkk++) {
            int kk = c * 32 + hkk * 16;
            unsigned a16[4];
            unsigned aaddr = sbase + AH_OFF +
                ((wm * 16 + (lane & 15)) * A_STR + kk + ((lane >> 4) << 3)) * 2;
            ldsm4(a16, aaddr);

            #pragma unroll
            for (int nb = 0; nb < 8; nb++) {
                int n0 = wn * 128 + nb * 16;
                unsigned baddr = bhb +
                    ((lane & 15) * A_STR + hkk * 16 + 0 + ((lane >> 4) << 3)) * 2
                    + 0;
                // B fragment at (row = hkk*16 + lane&15? no) -- B rows are k,
                // so row index = hkk*16 + (lane & 15), col = n0
                baddr = bhb +
                    (((hkk * 16) + (lane & 15)) * A_STR + n0 + ((lane >> 4) << 3)) * 2;
                unsigned bh4[4];
                ldsm4t(bh4, baddr);
                mma_fp16(acc[nb * 2],     a16, bh4[0], bh4[1]);
                mma_fp16(acc[nb * 2 + 1], a16, bh4[2], bh4[3]);
            }
        }
    }
    __syncthreads();   // all warps done reading A before caller rewrites it
}

__global__ void __launch_bounds__(256, 2)
out_kernel(const float* __restrict__ m,
           const float* __restrict__ bg,
           const float* __restrict__ bo,
           float* __restrict__ out) {
    extern __shared__ char smc[];
    unsigned sbase = (unsigned)__cvta_generic_to_shared(smc);
    float* sBG = reinterpret_cast<float*>(smc + BG_OFF);
    float* sOV = reinterpret_cast<float*>(smc + OV_OFF);
    float* sBO = reinterpret_cast<float*>(smc + BO_OFF);

    int t = threadIdx.x;
    int lane = t & 31, wid = t >> 5;
    int wm = wid >> 1, wn = wid & 1;
    int n = blockIdx.y;
    long tok0 = (long)n * SLEN + (long)blockIdx.x * 64;

    sBG[t] = bg[t];
    sOV[t] = g_o_buf[n * HC + t];
    sBO[t] = bo[t];

    // load m tile [64][256] fp32 once -> fp16 smem (GEMM1 operand)
    #pragma unroll
    for (int i = 0; i < 16; i++) {
        int idx = t + i * 256;
        int row = idx >> 6;
        int c4  = (idx & 63) << 2;
        float4 v = *reinterpret_cast<const float4*>(m + (tok0 + row) * CIN + c4);
        char* p = smc + AH_OFF + (row * A_STR + c4) * 2;
        reinterpret_cast<__half2*>(p)[0] = __floats2half2_rn(v.x, v.y);
        reinterpret_cast<__half2*>(p)[1] = __floats2half2_rn(v.z, v.w);
    }
    __syncthreads();

    float acc[16][4];
    #pragma unroll
    for (int i = 0; i < 16; i++)
        #pragma unroll
        for (int j = 0; j < 4; j++) acc[i][j] = 0.f;

    // ---- GEMM1: x = M @ Wg (tail prefetches Wo chunk 0) ----
    gemm_fp16x1(sbase, g_Wg16, acc, t, lane, wm, wn, false, g_Wo16);

    // ---- epilogue 1: G = ov * sigmoid(acc + bg) -> fp16 A tile ----
    #pragma unroll
    for (int nt = 0; nt < 16; nt++) {
        int col0 = wn * 128 + nt * 8 + (lane & 3) * 2;
        int r0   = wm * 16 + (lane >> 2);
        float bg0 = sBG[col0], bg1 = sBG[col0 + 1];
        float ov0 = sOV[col0], ov1 = sOV[col0 + 1];
        float g0 = ov0 / (1.f + __expf(-(acc[nt][0] + bg0)));
        float g1 = ov1 / (1.f + __expf(-(acc[nt][1] + bg1)));
        float g2 = ov0 / (1.f + __expf(-(acc[nt][2] + bg0)));
        float g3 = ov1 / (1.f + __expf(-(acc[nt][3] + bg1)));
        *reinterpret_cast<__half2*>(smc + AH_OFF + (r0 * A_STR + col0) * 2)
            = __floats2half2_rn(g0, g1);
        *reinterpret_cast<__half2*>(smc + AH_OFF + ((r0 + 8) * A_STR + col0) * 2)
            = __floats2half2_rn(g2, g3);
        acc[nt][0] = acc[nt][1] = acc[nt][2] = acc[nt][3] = 0.f;
    }
    __syncthreads();

    // ---- GEMM2: out = G @ Wo (chunk 0 already in flight) ----
    gemm_fp16x1(sbase, g_Wo16, acc, t, lane, wm, wn, true, (const __half*)0);

    // ---- epilogue 2: + bo, write out ----
    #pragma unroll
    for (int nt = 0; nt < 16; nt++) {
        int col0 = wn * 128 + nt * 8 + (lane & 3) * 2;
        int r0   = wm * 16 + (lane >> 2);
        float2 o0 = make_float2(acc[nt][0] + sBO[col0], acc[nt][1] + sBO[col0 + 1]);
        float2 o1 = make_float2(acc[nt][2] + sBO[col0], acc[nt][3] + sBO[col0 + 1]);
        *reinterpret_cast<float2*>(out + (tok0 + r0) * CIN + col0)     = o0;
        *reinterpret_cast<float2*>(out + (tok0 + r0 + 8) * CIN + col0) = o1;
    }
}

// ---------------------------------------------------------------------------
extern "C" void kernel_launch(void* const* d_in, const int* in_sizes, int n_in,
                              void* d_out, int out_size) {
    const float* m    = (const float*)d_in[0];
    const float* mask = (const float*)d_in[1];
    const float* Wq   = (const float*)d_in[2];
    const float* Wk   = (const float*)d_in[3];
    const float* Wv   = (const float*)d_in[4];
    const float* Wg   = (const float*)d_in[5];
    const float* bg   = (const float*)d_in[6];
    const float* Wo   = (const float*)d_in[7];
    const float* bo   = (const float*)d_in[8];
    float* out = (float*)d_out;

    wconv_kernel<<<64, 256>>>(Wg, Wo, Wk, Wv);

    cudaFuncSetAttribute(kv_kernel,
                         cudaFuncAttributeMaxDynamicSharedMemorySize, KV_SMEM);
    kv_kernel<<<(NROWS * SLEN) / 64, 256, KV_SMEM>>>(m, mask);

    q2_kernel<<<NROWS, 256>>>(Wq);

    attn_part_kernel<<<dim3(NROWS, 4), 256>>>(mask);
    attn_merge_kernel<<<NROWS, 256>>>();

    cudaFuncSetAttribute(out_kernel,
                         cudaFuncAttributeMaxDynamicSharedMemorySize, SMEM_BYTES);
    out_kernel<<<dim3(SLEN / 64, NROWS), 256, SMEM_BYTES>>>(m, bg, bo, out);
}

// round 16
// speedup vs baseline: 2.3111x; 1.0586x over previous
#include <cuda_runtime.h>
#include <cuda_bf16.h>
#include <cuda_fp16.h>
#include <math.h>

#define NROWS 384
#define SLEN  1024
#define CIN   256
#define CH    32
#define NH    8
#define HC    256   // NH*CH

// Scratch (no cudaMalloc allowed).
__device__ float g_q_buf[NROWS * HC];
__device__ float g_o_buf[NROWS * HC];
__device__ float g_k_buf[(size_t)NROWS * SLEN * CH];
__device__ float g_v_buf[(size_t)NROWS * SLEN * CH];
// Weights, all fp16 single-MMA paths (error budget calibrated R12-R14):
__device__ __half g_Wg16[CIN * HC];
__device__ __half g_Wo16[HC * CIN];
__device__ __half g_Wkv16[CIN * 64];          // Wk|Wv combined, [K,64]
// Masked-mean partials: [tile 0..15][n][c] and [tile][n]
__device__ float g_qpart[16 * NROWS * CIN];
__device__ float g_mpart[16 * NROWS];
// Split-S attention partials: [quarter][n][hc] and stats [quarter][n][h][2]
__device__ float g_opart[4 * NROWS * HC];
__device__ float g_stat[4 * NROWS * NH * 2];

// ---------------------------------------------------------------------------
// cp.async helpers
// ---------------------------------------------------------------------------
__device__ __forceinline__ void cp16(unsigned saddr, const void* g) {
    asm volatile("cp.async.cg.shared.global [%0], [%1], 16;" :: "r"(saddr), "l"(g));
}
#define CP_COMMIT() asm volatile("cp.async.commit_group;" ::: "memory")
#define CP_WAIT1()  asm volatile("cp.async.wait_group 1;" ::: "memory")
#define CP_WAIT0()  asm volatile("cp.async.wait_group 0;" ::: "memory")

// ---------------------------------------------------------------------------
// Kernel 0: weight conversion (all fp16)
// ---------------------------------------------------------------------------
__global__ void wconv_kernel(const float* __restrict__ Wg,
                             const float* __restrict__ Wo,
                             const float* __restrict__ Wk,
                             const float* __restrict__ Wv) {
    int i = (blockIdx.x * 256 + threadIdx.x) * 4;  // 65536 elems per big matrix
    {
        float4 v = *reinterpret_cast<const float4*>(Wg + i);
        *reinterpret_cast<__half2*>(g_Wg16 + i)     = __floats2half2_rn(v.x, v.y);
        *reinterpret_cast<__half2*>(g_Wg16 + i + 2) = __floats2half2_rn(v.z, v.w);
    }
    {
        float4 v = *reinterpret_cast<const float4*>(Wo + i);
        *reinterpret_cast<__half2*>(g_Wo16 + i)     = __floats2half2_rn(v.x, v.y);
        *reinterpret_cast<__half2*>(g_Wo16 + i + 2) = __floats2half2_rn(v.z, v.w);
    }
    if (i < CIN * 64) {  // combined Wk|Wv: row k, col j (j<32 => Wk, else Wv)
        int k = i >> 6, j = i & 63;
        float4 v = (j < 32)
            ? *reinterpret_cast<const float4*>(Wk + k * CH + j)
            : *reinterpret_cast<const float4*>(Wv + k * CH + (j - 32));
        *reinterpret_cast<__half2*>(g_Wkv16 + i)     = __floats2half2_rn(v.x, v.y);
        *reinterpret_cast<__half2*>(g_Wkv16 + i + 2) = __floats2half2_rn(v.z, v.w);
    }
}

// ---------------------------------------------------------------------------
// mma helpers
// ---------------------------------------------------------------------------
__device__ __forceinline__ void ldsm4(unsigned r[4], unsigned addr) {
    asm volatile("ldmatrix.sync.aligned.m8n8.x4.shared.b16 {%0,%1,%2,%3}, [%4];"
        : "=r"(r[0]), "=r"(r[1]), "=r"(r[2]), "=r"(r[3]) : "r"(addr));
}
__device__ __forceinline__ void ldsm4t(unsigned r[4], unsigned addr) {
    asm volatile("ldmatrix.sync.aligned.m8n8.x4.trans.shared.b16 {%0,%1,%2,%3}, [%4];"
        : "=r"(r[0]), "=r"(r[1]), "=r"(r[2]), "=r"(r[3]) : "r"(addr));
}
__device__ __forceinline__ void mma_fp16(float c[4], const unsigned a[4],
                                         unsigned b0, unsigned b1) {
    asm volatile("mma.sync.aligned.m16n8k16.row.col.f32.f16.f16.f32 "
        "{%0,%1,%2,%3}, {%4,%5,%6,%7}, {%8,%9}, {%0,%1,%2,%3};"
        : "+f"(c[0]), "+f"(c[1]), "+f"(c[2]), "+f"(c[3])
        : "r"(a[0]), "r"(a[1]), "r"(a[2]), "r"(a[3]), "r"(b0), "r"(b1));
}

// ---------------------------------------------------------------------------
// Kernel 2: k|v = m @ (Wk|Wv), fp16 single-MMA + fused masked-mean partials.
// (unchanged from R14 — passing; 2-stage pipeline uses WAIT0 every chunk)
// ---------------------------------------------------------------------------
#define KA_STR  264
#define KB_STR  72
#define KB0_OFF 33792             // stage s at KB0 + s*2304 (fp16 [16][64])
#define KV_SMEM 38400

__device__ __forceinline__ void kv_prefetch(unsigned sbase, int stage, int kk, int t) {
    if (t < 128) {
        int row = t >> 3, c8 = (t & 7) << 3;
        cp16(sbase + KB0_OFF + stage * 2304 + (row * KB_STR + c8) * 2,
             g_Wkv16 + (kk + row) * 64 + c8);
    }
}

__global__ void __launch_bounds__(256, 3)
kv_kernel(const float* __restrict__ m, const float* __restrict__ mask) {
    extern __shared__ char smc[];
    __shared__ float mask_sm[64];
    unsigned sbase = (unsigned)__cvta_generic_to_shared(smc);
    int t = threadIdx.x;
    int lane = t & 31, wid = t >> 5;
    int wm = wid >> 1, wn = wid & 1;
    int n    = blockIdx.x >> 4;
    int tile = blockIdx.x & 15;
    long r0g = (long)blockIdx.x * 64;

    if (t < 64) mask_sm[t] = mask[(size_t)n * SLEN + tile * 64 + t];

    // load m tile [64][256] fp32 -> fp16 smem
    #pragma unroll
    for (int i = 0; i < 16; i++) {
        int idx = t + i * 256;
        int row = idx >> 6;
        int c4  = (idx & 63) << 2;
        float4 v = *reinterpret_cast<const float4*>(m + (r0g + row) * CIN + c4);
        char* p = smc + (row * KA_STR + c4) * 2;
        reinterpret_cast<__half2*>(p)[0] = __floats2half2_rn(v.x, v.y);
        reinterpret_cast<__half2*>(p)[1] = __floats2half2_rn(v.z, v.w);
    }
    __syncthreads();

    kv_prefetch(sbase, 0, 0, t);
    CP_COMMIT();

    // masked-mean partial for channel t over this CTA's 64 tokens
    {
        float qs = 0.f;
        #pragma unroll 8
        for (int r = 0; r < 64; r++) {
            float mv = __half2float(*reinterpret_cast<__half*>(
                smc + (r * KA_STR + t) * 2));
            qs = fmaf(mv, mask_sm[r], qs);
        }
        g_qpart[(tile * NROWS + n) * CIN + t] = qs;
        if (t == 0) {
            float ms = 0.f;
            for (int r = 0; r < 64; r++) ms += mask_sm[r];
            g_mpart[tile * NROWS + n] = ms;
        }
    }

    float acc[4][4];
    #pragma unroll
    for (int i = 0; i < 4; i++)
        #pragma unroll
        for (int j = 0; j < 4; j++) acc[i][j] = 0.f;

    for (int c = 0; c < 16; c++) {
        CP_WAIT0();
        __syncthreads();
        if (c < 15) { kv_prefetch(sbase, (c + 1) & 1, (c + 1) * 16, t); CP_COMMIT(); }
        int kk = c * 16;
        unsigned kbh = sbase + KB0_OFF + (c & 1) * 2304;

        unsigned a16[4];
        unsigned aaddr = sbase +
            ((wm * 16 + (lane & 15)) * KA_STR + kk + ((lane >> 4) << 3)) * 2;
        ldsm4(a16, aaddr);

        #pragma unroll
        for (int nb = 0; nb < 2; nb++) {
            int col0 = wn * 32 + nb * 16;
            unsigned baddr = kbh +
                ((lane & 15) * KB_STR + col0 + ((lane >> 4) << 3)) * 2;
            unsigned bh[4];
            ldsm4t(bh, baddr);
            mma_fp16(acc[nb * 2],     a16, bh[0], bh[1]);
            mma_fp16(acc[nb * 2 + 1], a16, bh[2], bh[3]);
        }
    }

    // write k (cols 0..31) and v (cols 32..63)
    #pragma unroll
    for (int nb = 0; nb < 2; nb++) {
        #pragma unroll
        for (int half = 0; half < 2; half++) {
            int col = wn * 32 + nb * 16 + half * 8 + (lane & 3) * 2;
            int r0  = wm * 16 + (lane >> 2);
            float* f = acc[nb * 2 + half];
            float* dst = (col < CH) ? (g_k_buf + ((r0g + r0) * CH + col))
                                    : (g_v_buf + ((r0g + r0) * CH + col - CH));
            *reinterpret_cast<float2*>(dst) = make_float2(f[0], f[1]);
            dst += 8 * CH;
            *reinterpret_cast<float2*>(dst) = make_float2(f[2], f[3]);
        }
    }
}

// ---------------------------------------------------------------------------
// Kernel 2b: finish mean + q = (mean @ Wq) * C^-0.5
// ---------------------------------------------------------------------------
__global__ void q2_kernel(const float* __restrict__ Wq) {
    int n = blockIdx.x, t = threadIdx.x;
    __shared__ float qm[CIN];
    float s = 0.f;
    #pragma unroll
    for (int p = 0; p < 16; p++) s += g_qpart[(p * NROWS + n) * CIN + t];
    float mk = 0.f;
    #pragma unroll
    for (int p = 0; p < 16; p++) mk += g_mpart[p * NROWS + n];
    qm[t] = s / (mk + 1e-10f);
    __syncthreads();
    float acc = 0.f;
    #pragma unroll 8
    for (int c = 0; c < CIN; c++) acc = fmaf(qm[c], Wq[c * HC + t], acc);
    g_q_buf[n * HC + t] = acc * 0.17677669529663687f;
}

// ---------------------------------------------------------------------------
// Kernel 3a: split-S attention partials, 4 quarters. grid (384, 4).
// ---------------------------------------------------------------------------
#define S4 256

__global__ void __launch_bounds__(256)
attn_part_kernel(const float* __restrict__ mask) {
    int n = blockIdx.x, qt = blockIdx.y, t = threadIdx.x;
    int s0 = qt * S4;
    __shared__ float q_sm[HC];
    __shared__ float p_sm[NH * S4];   // 8 KB

    q_sm[t] = g_q_buf[n * HC + t];
    __syncthreads();

    const float* krow = g_k_buf + ((size_t)n * SLEN + s0) * CH;
    const float* vrow = g_v_buf + ((size_t)n * SLEN + s0) * CH;
    const float* mk   = mask + (size_t)n * SLEN + s0;

    {
        int s = t;
        float kreg[32];
        #pragma unroll
        for (int q = 0; q < 8; q++)
            *reinterpret_cast<float4*>(kreg + q * 4) =
                *reinterpret_cast<const float4*>(krow + (size_t)s * CH + q * 4);
        float bias = 1e9f * (mk[s] - 1.0f);
        #pragma unroll
        for (int h = 0; h < NH; h++) {
            float d = 0.f;
            #pragma unroll
            for (int j = 0; j < 32; j++) d = fmaf(q_sm[h * 32 + j], kreg[j], d);
            p_sm[h * S4 + s] = d + bias;
        }
    }
    __syncthreads();

    int h = t >> 5, lane = t & 31;
    float mx = -3.0e38f;
    for (int s = lane; s < S4; s += 32) mx = fmaxf(mx, p_sm[h * S4 + s]);
    #pragma unroll
    for (int off = 16; off > 0; off >>= 1)
        mx = fmaxf(mx, __shfl_xor_sync(0xffffffffu, mx, off));

    float sum = 0.f;
    for (int s = lane; s < S4; s += 32) {
        float e = __expf(p_sm[h * S4 + s] - mx);
        p_sm[h * S4 + s] = e;
        sum += e;
    }
    #pragma unroll
    for (int off = 16; off > 0; off >>= 1)
        sum += __shfl_xor_sync(0xffffffffu, sum, off);
    if (lane == 0) {
        g_stat[((qt * NROWS + n) * NH + h) * 2]     = mx;
        g_stat[((qt * NROWS + n) * NH + h) * 2 + 1] = sum;
    }
    __syncthreads();

    // unnormalized p@v partial
    {
        int sg  = lane >> 3;
        int c4  = (lane & 7) << 2;
        float4 acc4 = make_float4(0.f, 0.f, 0.f, 0.f);
        const float* ph = p_sm + h * S4;
        #pragma unroll 4
        for (int s = sg; s < S4; s += 4) {
            float p = ph[s];
            float4 v4 = *reinterpret_cast<const float4*>(vrow + (size_t)s * CH + c4);
            acc4.x = fmaf(p, v4.x, acc4.x);
            acc4.y = fmaf(p, v4.y, acc4.y);
            acc4.z = fmaf(p, v4.z, acc4.z);
            acc4.w = fmaf(p, v4.w, acc4.w);
        }
        #pragma unroll
        for (int off = 8; off <= 16; off <<= 1) {
            acc4.x += __shfl_xor_sync(0xffffffffu, acc4.x, off);
            acc4.y += __shfl_xor_sync(0xffffffffu, acc4.y, off);
            acc4.z += __shfl_xor_sync(0xffffffffu, acc4.z, off);
            acc4.w += __shfl_xor_sync(0xffffffffu, acc4.w, off);
        }
        if (sg == 0)
            *reinterpret_cast<float4*>(
                g_opart + (qt * NROWS + n) * HC + h * CH + c4) = acc4;
    }
}

// ---------------------------------------------------------------------------
// Kernel 3b: merge the four S-quarters
// ---------------------------------------------------------------------------
__global__ void attn_merge_kernel() {
    int n = blockIdx.x, t = threadIdx.x;
    int h = t >> 5;
    float mq[4], sq[4];
    #pragma unroll
    for (int p = 0; p < 4; p++) {
        mq[p] = g_stat[((p * NROWS + n) * NH + h) * 2];
        sq[p] = g_stat[((p * NROWS + n) * NH + h) * 2 + 1];
    }
    float M = fmaxf(fmaxf(mq[0], mq[1]), fmaxf(mq[2], mq[3]));
    float num = 0.f, den = 0.f;
    #pragma unroll
    for (int p = 0; p < 4; p++) {
        float w = __expf(mq[p] - M);
        num = fmaf(w, g_opart[(p * NROWS + n) * HC + t], num);
        den = fmaf(w, sq[p], den);
    }
    g_o_buf[n * HC + t] = num / den;
}

// ---------------------------------------------------------------------------
// Kernel 4: out_kernel, fp16 single-MMA, BK=32, 3-stage cp.async, warp tile
// 32x64 (2x4 layout: 6 ldmatrix per k16).  BM=64, 256 threads, 2 CTAs/SM.
// RACE FIX vs R15: last chunk's group (chunk 7, committed at iter 5) is the
// ONLY pending group at iter 7, so wait_group 1 was a no-op there -> stale
// reads.  Iter 7 now uses wait_group 0 (full drain; the Wnext commit happens
// after the wait, so cross-GEMM overlap is preserved).
// ---------------------------------------------------------------------------
#define A_STR   264
#define AH_OFF  0                 // fp16 m tile, then fp16 G tile (33792 B)
#define B0_OFF  33792             // stage s at B0 + s*16896 (fp16 [32][256])
#define STG_SZ  16896
#define BG_OFF  84480
#define OV_OFF  85504
#define BO_OFF  86528
#define SMEM_BYTES 87552

__device__ __forceinline__ void out_prefetch32(unsigned sbase, int stage,
        const __half* __restrict__ W16, int kk, int t) {
    unsigned bh = sbase + B0_OFF + stage * STG_SZ;
    #pragma unroll
    for (int i = 0; i < 4; i++) {
        int f = t + i * 256;          // 0..1023
        int row = f >> 5, c8 = (f & 31) << 3;
        cp16(bh + (row * A_STR + c8) * 2, W16 + (kk + row) * 256 + c8);
    }
}

// One 64x256x256 fp16 GEMM, BK=32, 3-stage pipeline.
__device__ __forceinline__ void gemm_fp16x1(
    unsigned sbase, const __half* __restrict__ W16,
    float acc[16][4], int t, int lane, int wm, int wn, bool pre0,
    const __half* __restrict__ Wnext)
{
    if (!pre0) { out_prefetch32(sbase, 0, W16, 0, t); CP_COMMIT(); }
    out_prefetch32(sbase, 1, W16, 32, t); CP_COMMIT();
    for (int c = 0; c < 8; c++) {
        if (c == 7) CP_WAIT0();   // chunk 7's group is the only one pending
        else        CP_WAIT1();   // chunk c done; chunk c+1 may stay in flight
        __syncthreads();
        int pstage = (c + 2) % 3;   // stage of chunk c+2 (== (c-1)%3, freed at c-1)
        if (c < 6)       { out_prefetch32(sbase, pstage, W16, (c + 2) * 32, t); CP_COMMIT(); }
        else if (c == 7 && Wnext) { out_prefetch32(sbase, 0, Wnext, 0, t); CP_COMMIT(); }
        unsigned bhb = sbase + B0_OFF + (c % 3) * STG_SZ;

        #pragma unroll
        for (int hkk = 0; hkk < 2; hkk++) {
            int kk = c * 32 + hkk * 16;
            unsigned a0[4], a1[4];
            unsigned abase = sbase + AH_OFF +
                ((wm * 32 + (lane & 15)) * A_STR + kk + ((lane >> 4) << 3)) * 2;
            ldsm4(a0, abase);
            ldsm4(a1, abase + 16 * A_STR * 2);

            #pragma unroll
            for (int j = 0; j < 4; j++) {
                int n0 = wn * 64 + j * 16;
                unsigned baddr = bhb +
                    ((hkk * 16 + (lane & 15)) * A_STR + n0 + ((lane >> 4) << 3)) * 2;
                unsigned bh4[4];
                ldsm4t(bh4, baddr);
                mma_fp16(acc[j * 2],     a0, bh4[0], bh4[1]);
                mma_fp16(acc[j * 2 + 1], a0, bh4[2], bh4[3]);
                mma_fp16(acc[8 + j * 2],     a1, bh4[0], bh4[1]);
                mma_fp16(acc[8 + j * 2 + 1], a1, bh4[2], bh4[3]);
            }
        }
    }
    __syncthreads();   // all warps done reading A before caller rewrites it
}

__global__ void __launch_bounds__(256, 2)
out_kernel(const float* __restrict__ m,
           const float* __restrict__ bg,
           const float* __restrict__ bo,
           float* __restrict__ out) {
    extern __shared__ char smc[];
    unsigned sbase = (unsigned)__cvta_generic_to_shared(smc);
    float* sBG = reinterpret_cast<float*>(smc + BG_OFF);
    float* sOV = reinterpret_cast<float*>(smc + OV_OFF);
    float* sBO = reinterpret_cast<float*>(smc + BO_OFF);

    int t = threadIdx.x;
    int lane = t & 31, wid = t >> 5;
    int wm = wid >> 2, wn = wid & 3;   // 2 (m=32 rows) x 4 (n=64 cols)
    int n = blockIdx.y;
    long tok0 = (long)n * SLEN + (long)blockIdx.x * 64;

    sBG[t] = bg[t];
    sOV[t] = g_o_buf[n * HC + t];
    sBO[t] = bo[t];

    // load m tile [64][256] fp32 once -> fp16 smem (GEMM1 operand)
    #pragma unroll
    for (int i = 0; i < 16; i++) {
        int idx = t + i * 256;
        int row = idx >> 6;
        int c4  = (idx & 63) << 2;
        float4 v = *reinterpret_cast<const float4*>(m + (tok0 + row) * CIN + c4);
        char* p = smc + AH_OFF + (row * A_STR + c4) * 2;
        reinterpret_cast<__half2*>(p)[0] = __floats2half2_rn(v.x, v.y);
        reinterpret_cast<__half2*>(p)[1] = __floats2half2_rn(v.z, v.w);
    }
    __syncthreads();

    float acc[16][4];
    #pragma unroll
    for (int i = 0; i < 16; i++)
        #pragma unroll
        for (int j = 0; j < 4; j++) acc[i][j] = 0.f;

    // ---- GEMM1: x = M @ Wg (tail prefetches Wo chunk 0) ----
    gemm_fp16x1(sbase, g_Wg16, acc, t, lane, wm, wn, false, g_Wo16);

    // ---- epilogue 1: G = ov * sigmoid(acc + bg) -> fp16 A tile ----
    #pragma unroll
    for (int i = 0; i < 2; i++)
    #pragma unroll
    for (int j = 0; j < 4; j++)
    #pragma unroll
    for (int half = 0; half < 2; half++) {
        float* a = acc[i * 8 + j * 2 + half];
        int col0 = wn * 64 + j * 16 + half * 8 + (lane & 3) * 2;
        int r0   = wm * 32 + i * 16 + (lane >> 2);
        float bg0 = sBG[col0], bg1 = sBG[col0 + 1];
        float ov0 = sOV[col0], ov1 = sOV[col0 + 1];
        float g0 = ov0 / (1.f + __expf(-(a[0] + bg0)));
        float g1 = ov1 / (1.f + __expf(-(a[1] + bg1)));
        float g2 = ov0 / (1.f + __expf(-(a[2] + bg0)));
        float g3 = ov1 / (1.f + __expf(-(a[3] + bg1)));
        *reinterpret_cast<__half2*>(smc + AH_OFF + (r0 * A_STR + col0) * 2)
            = __floats2half2_rn(g0, g1);
        *reinterpret_cast<__half2*>(smc + AH_OFF + ((r0 + 8) * A_STR + col0) * 2)
            = __floats2half2_rn(g2, g3);
        a[0] = a[1] = a[2] = a[3] = 0.f;
    }
    __syncthreads();

    // ---- GEMM2: out = G @ Wo (chunk 0 already in flight) ----
    gemm_fp16x1(sbase, g_Wo16, acc, t, lane, wm, wn, true, (const __half*)0);

    // ---- epilogue 2: + bo, write out ----
    #pragma unroll
    for (int i = 0; i < 2; i++)
    #pragma unroll
    for (int j = 0; j < 4; j++)
    #pragma unroll
    for (int half = 0; half < 2; half++) {
        float* a = acc[i * 8 + j * 2 + half];
        int col0 = wn * 64 + j * 16 + half * 8 + (lane & 3) * 2;
        int r0   = wm * 32 + i * 16 + (lane >> 2);
        float2 o0 = make_float2(a[0] + sBO[col0], a[1] + sBO[col0 + 1]);
        float2 o1 = make_float2(a[2] + sBO[col0], a[3] + sBO[col0 + 1]);
        *reinterpret_cast<float2*>(out + (tok0 + r0) * CIN + col0)     = o0;
        *reinterpret_cast<float2*>(out + (tok0 + r0 + 8) * CIN + col0) = o1;
    }
}

// ---------------------------------------------------------------------------
extern "C" void kernel_launch(void* const* d_in, const int* in_sizes, int n_in,
                              void* d_out, int out_size) {
    const float* m    = (const float*)d_in[0];
    const float* mask = (const float*)d_in[1];
    const float* Wq   = (const float*)d_in[2];
    const float* Wk   = (const float*)d_in[3];
    const float* Wv   = (const float*)d_in[4];
    const float* Wg   = (const float*)d_in[5];
    const float* bg   = (const float*)d_in[6];
    const float* Wo   = (const float*)d_in[7];
    const float* bo   = (const float*)d_in[8];
    float* out = (float*)d_out;

    wconv_kernel<<<64, 256>>>(Wg, Wo, Wk, Wv);

    cudaFuncSetAttribute(kv_kernel,
                         cudaFuncAttributeMaxDynamicSharedMemorySize, KV_SMEM);
    kv_kernel<<<(NROWS * SLEN) / 64, 256, KV_SMEM>>>(m, mask);

    q2_kernel<<<NROWS, 256>>>(Wq);

    attn_part_kernel<<<dim3(NROWS, 4), 256>>>(mask);
    attn_merge_kernel<<<NROWS, 256>>>();

    cudaFuncSetAttribute(out_kernel,
                         cudaFuncAttributeMaxDynamicSharedMemorySize, SMEM_BYTES);
    out_kernel<<<dim3(SLEN / 64, NROWS), 256, SMEM_BYTES>>>(m, bg, bo, out);
}